// round 10
// baseline (speedup 1.0000x reference)
#include <cuda_runtime.h>
#include <cuda_fp16.h>
#include <cstdint>

#define NA 100000
#define NB 100000
#define IN_DIM 256
#define OUT_DIM 256
#define NE 320000
#define LN_EPS 1e-5f

#define NBIN (2 * NA)
#define SCAN_B 512
#define NBLK ((NBIN + SCAN_B - 1) / SCAN_B)   // 391

// fused GEMM+finalize geometry
#define TM 64
#define MT ((NA + TM - 1) / TM)               // 1563 row-block CTAs
#define ZB_BLOCKS ((int)(((size_t)NB * OUT_DIM / 4 + 511) / 512))  // 12500
#define SM_A   0                              // A: 2 paths x 4 kc64 x 64 rows x 128B = 65536
#define SM_B   65536                          // B: 2 stages x 16384
#define SM_ACC 98304                          // accum: 64 x 512 fp32 = 131072
#define FSM_TOTAL 229376

// ---------------- scratch (device globals; no allocation allowed) -----------
__device__ float g_cnt[NBIN];                 // 1.0 if deg>0 else 0.0
__device__ __half g_Sh[(size_t)NBIN * 256];   // per-bin MEAN, fp16
__device__ __half g_Wt_hi[512 * 256];         // Wcat^T [n][k], fp16 hi
__device__ __half g_Wt_lo[512 * 256];         // fp16 lo residual
__device__ int g_hist[NBIN];
__device__ int g_rowptr[NBIN];
__device__ int g_cursor[NBIN];
__device__ int g_elist[2 * NE];
__device__ int g_blocksums[SCAN_B];
__device__ int g_blockoff[SCAN_B];

// ---------------- helpers ----------------------------------------------------
__device__ __forceinline__ uint32_t smem_u32(const void* p) {
    uint32_t a;
    asm("{ .reg .u64 t; cvta.to.shared.u64 t, %1; cvt.u32.u64 %0, t; }" : "=r"(a) : "l"(p));
    return a;
}
__device__ __forceinline__ void ldsm_x4(uint32_t& r0, uint32_t& r1, uint32_t& r2,
                                        uint32_t& r3, uint32_t addr) {
    asm volatile("ldmatrix.sync.aligned.m8n8.x4.shared.b16 {%0,%1,%2,%3}, [%4];"
                 : "=r"(r0), "=r"(r1), "=r"(r2), "=r"(r3) : "r"(addr));
}
__device__ __forceinline__ void mma_fp16(float* c, const uint32_t* a, const uint32_t* b) {
    asm volatile("mma.sync.aligned.m16n8k16.row.col.f32.f16.f16.f32 "
                 "{%0,%1,%2,%3}, {%4,%5,%6,%7}, {%8,%9}, {%0,%1,%2,%3};"
                 : "+f"(c[0]), "+f"(c[1]), "+f"(c[2]), "+f"(c[3])
                 : "r"(a[0]), "r"(a[1]), "r"(a[2]), "r"(a[3]), "r"(b[0]), "r"(b[1]));
}
#define CP_ASYNC16(sm, gp) \
    asm volatile("cp.async.cg.shared.global [%0], [%1], 16;" \
                 :: "r"(sm), "l"(gp) : "memory")
#define CP_ASYNC16Z(sm, gp, sz) \
    asm volatile("cp.async.cg.shared.global [%0], [%1], 16, %2;" \
                 :: "r"(sm), "l"(gp), "r"(sz) : "memory")
#define CP_COMMIT() asm volatile("cp.async.commit_group;" ::: "memory")
#define CP_WAIT0()  asm volatile("cp.async.wait_group 0;" ::: "memory")
#define CP_WAIT1()  asm volatile("cp.async.wait_group 1;" ::: "memory")

// ---------------- zero hist ---------------------------------------------------
__global__ __launch_bounds__(256) void zero_hist_kernel() {
    size_t i = (size_t)blockIdx.x * 256 + threadIdx.x;
    if (i < NBIN / 4)
        reinterpret_cast<int4*>(g_hist)[i] = make_int4(0, 0, 0, 0);
}

// ---------------- W split/transpose prep ------------------------------------
__global__ __launch_bounds__(256) void splitW_kernel(const float* __restrict__ W0,
                                                     const float* __restrict__ W1) {
    int n = blockIdx.x;
    int k = threadIdx.x;
    float w = (n < 256) ? W0[k * 256 + n] : W1[k * 256 + (n - 256)];
    __half h = __float2half_rn(w);
    float r = w - __half2float(h);
    g_Wt_hi[n * 256 + k] = h;
    g_Wt_lo[n * 256 + k] = __float2half_rn(r);
}

// ---------------- CSR build --------------------------------------------------
__global__ __launch_bounds__(256) void hist_kernel(
    const int* __restrict__ ei0, const int* __restrict__ ei1)
{
    int i = blockIdx.x * 256 + threadIdx.x;
    if (i >= 2 * NE) return;
    int p = (i >= NE) ? 1 : 0;
    int e = i - p * NE;
    const int* __restrict__ ei = p ? ei1 : ei0;
    int dst = ei[e + NE];
    atomicAdd(&g_hist[p * NA + dst], 1);
}

__global__ __launch_bounds__(SCAN_B) void scanA_kernel() {
    __shared__ int sh[SCAN_B];
    int i = blockIdx.x * SCAN_B + threadIdx.x;
    sh[threadIdx.x] = (i < NBIN) ? g_hist[i] : 0;
    __syncthreads();
    for (int d = SCAN_B / 2; d > 0; d >>= 1) {
        if (threadIdx.x < d) sh[threadIdx.x] += sh[threadIdx.x + d];
        __syncthreads();
    }
    if (threadIdx.x == 0) g_blocksums[blockIdx.x] = sh[0];
}

__global__ __launch_bounds__(SCAN_B) void scanB_kernel() {
    __shared__ int sh[SCAN_B];
    int tid = threadIdx.x;
    int v = (tid < NBLK) ? g_blocksums[tid] : 0;
    sh[tid] = v;
    __syncthreads();
    for (int d = 1; d < SCAN_B; d <<= 1) {
        int t = (tid >= d) ? sh[tid - d] : 0;
        __syncthreads();
        sh[tid] += t;
        __syncthreads();
    }
    if (tid < NBLK) g_blockoff[tid] = sh[tid] - v;
}

__global__ __launch_bounds__(SCAN_B) void scanC_kernel() {
    __shared__ int sh[SCAN_B];
    int tid = threadIdx.x;
    int i = blockIdx.x * SCAN_B + tid;
    int v = (i < NBIN) ? g_hist[i] : 0;
    sh[tid] = v;
    __syncthreads();
    for (int d = 1; d < SCAN_B; d <<= 1) {
        int t = (tid >= d) ? sh[tid - d] : 0;
        __syncthreads();
        sh[tid] += t;
        __syncthreads();
    }
    if (i < NBIN) {
        int excl = sh[tid] - v + g_blockoff[blockIdx.x];
        g_rowptr[i] = excl;
        g_cursor[i] = excl;
        g_cnt[i] = (v > 0) ? 1.0f : 0.0f;
    }
}

__global__ __launch_bounds__(256) void fill_kernel(
    const int* __restrict__ ei0, const int* __restrict__ ei1)
{
    int i = blockIdx.x * 256 + threadIdx.x;
    if (i >= 2 * NE) return;
    int p = (i >= NE) ? 1 : 0;
    int e = i - p * NE;
    const int* __restrict__ ei = p ? ei1 : ei0;
    int src = ei[e];
    int dst = ei[e + NE];
    int pos = atomicAdd(&g_cursor[p * NA + dst], 1);
    g_elist[pos] = src;
}

// ---------------- aggregate: warp per bin; mean -> fp16 ----------------------
__global__ __launch_bounds__(256) void agg_kernel(const float* __restrict__ xB) {
    int w = (blockIdx.x * 256 + threadIdx.x) >> 5;
    int lane = threadIdx.x & 31;
    if (w >= NBIN) return;
    int start = g_rowptr[w];
    int deg = g_hist[w];

    float a[8] = {0.f, 0.f, 0.f, 0.f, 0.f, 0.f, 0.f, 0.f};

    int j = 0;
    for (; j + 4 <= deg; j += 4) {
        int s0 = __ldg(&g_elist[start + j]);
        int s1 = __ldg(&g_elist[start + j + 1]);
        int s2 = __ldg(&g_elist[start + j + 2]);
        int s3 = __ldg(&g_elist[start + j + 3]);
        const float4* r0 = reinterpret_cast<const float4*>(xB + (size_t)s0 * 256) + lane * 2;
        const float4* r1 = reinterpret_cast<const float4*>(xB + (size_t)s1 * 256) + lane * 2;
        const float4* r2 = reinterpret_cast<const float4*>(xB + (size_t)s2 * 256) + lane * 2;
        const float4* r3 = reinterpret_cast<const float4*>(xB + (size_t)s3 * 256) + lane * 2;
        float4 v0a = r0[0], v0b = r0[1];
        float4 v1a = r1[0], v1b = r1[1];
        float4 v2a = r2[0], v2b = r2[1];
        float4 v3a = r3[0], v3b = r3[1];
        a[0] += v0a.x + v1a.x + v2a.x + v3a.x;
        a[1] += v0a.y + v1a.y + v2a.y + v3a.y;
        a[2] += v0a.z + v1a.z + v2a.z + v3a.z;
        a[3] += v0a.w + v1a.w + v2a.w + v3a.w;
        a[4] += v0b.x + v1b.x + v2b.x + v3b.x;
        a[5] += v0b.y + v1b.y + v2b.y + v3b.y;
        a[6] += v0b.z + v1b.z + v2b.z + v3b.z;
        a[7] += v0b.w + v1b.w + v2b.w + v3b.w;
    }
    for (; j < deg; j++) {
        int src = __ldg(&g_elist[start + j]);
        const float4* r4 = reinterpret_cast<const float4*>(xB + (size_t)src * 256) + lane * 2;
        float4 v0 = r4[0], v1 = r4[1];
        a[0] += v0.x; a[1] += v0.y; a[2] += v0.z; a[3] += v0.w;
        a[4] += v1.x; a[5] += v1.y; a[6] += v1.z; a[7] += v1.w;
    }

    float inv = (deg > 0) ? 1.0f / (float)deg : 0.0f;
    __half2 h0 = __floats2half2_rn(a[0] * inv, a[1] * inv);
    __half2 h1 = __floats2half2_rn(a[2] * inv, a[3] * inv);
    __half2 h2 = __floats2half2_rn(a[4] * inv, a[5] * inv);
    __half2 h3 = __floats2half2_rn(a[6] * inv, a[7] * inv);
    uint4 hv;
    hv.x = *reinterpret_cast<uint32_t*>(&h0);
    hv.y = *reinterpret_cast<uint32_t*>(&h1);
    hv.z = *reinterpret_cast<uint32_t*>(&h2);
    hv.w = *reinterpret_cast<uint32_t*>(&h3);
    *reinterpret_cast<uint4*>(g_Sh + (size_t)w * 256 + lane * 8) = hv;
}

// ---------------- fused GEMM + finalize --------------------------------------
// CTA = 64 rows. 4 chunks (p,h) x 8 K-chunks(32) = 32 pipelined stages.
// A (both paths, all K) resident in smem; B double-buffered via cp.async.
// Partials parked in 128KB smem accumulator; finalize runs in-kernel.
__global__ __launch_bounds__(512, 1) void fused_kernel(
    const float* __restrict__ b0, const float* __restrict__ b1,
    const float* __restrict__ sem, const float* __restrict__ gamma,
    const float* __restrict__ beta,
    float* __restrict__ outA, float* __restrict__ outB)
{
    // trailing blocks: zero out_B
    if (blockIdx.x >= MT) {
        size_t i = (size_t)(blockIdx.x - MT) * 512 + threadIdx.x;
        if (i < (size_t)NB * OUT_DIM / 4)
            reinterpret_cast<float4*>(outB)[i] = make_float4(0.f, 0.f, 0.f, 0.f);
        return;
    }

    extern __shared__ char smem[];
    const uint32_t sbase = smem_u32(smem);
    const int tid = threadIdx.x, lane = tid & 31, wid = tid >> 5;
    const int wm = wid & 3;          // row group: wm*16
    const int wn = wid >> 2;         // col group: wn*32
    const int m0 = blockIdx.x * TM;

    const int am = lane & 15;
    const int aoff = lane >> 4;
    const int asw = am & 7;
    const int bn = (lane & 7) | ((lane & 16) >> 1);
    const int boff = (lane >> 3) & 1;
    const int bsw = bn & 7;

    // ---- issue A (both paths, full K) + B stage 0; then B stage 1 ----------
    {
#pragma unroll
        for (int l = 0; l < 8; l++) {
            int idx = l * 512 + tid;                 // 0..4095
            int pp = idx >> 11;
            int rem = idx & 2047;
            int c64 = rem >> 9;
            int rem2 = rem & 511;
            int r = rem2 >> 3, u = rem2 & 7;
            int grow = m0 + r;
            int ok = (grow < NA) ? 16 : 0;
            int grc = (grow < NA) ? grow : (NA - 1);
            uint32_t dst = sbase + SM_A + (uint32_t)(pp * 32768 + c64 * 8192 +
                            r * 128 + ((u ^ (r & 7)) << 4));
            const __half* src = g_Sh + ((size_t)pp * NA + grc) * 256 + c64 * 64 + u * 8;
            CP_ASYNC16Z(dst, src, ok);
        }
        // B stage 0 (chunk 0, c32 0)
#pragma unroll
        for (int l = 0; l < 2; l++) {
            int idx = l * 512 + tid;                 // 0..1023
            int n = idx >> 3, u = idx & 7;
            uint32_t dst = sbase + SM_B + (uint32_t)(n * 128 + ((u ^ (n & 7)) << 4));
            const __half* base = (u < 4) ? g_Wt_hi : g_Wt_lo;
            CP_ASYNC16(dst, base + (size_t)n * 256 + (u & 3) * 8);
        }
        CP_COMMIT();
        // B stage 1 (chunk 0, c32 1)
#pragma unroll
        for (int l = 0; l < 2; l++) {
            int idx = l * 512 + tid;
            int n = idx >> 3, u = idx & 7;
            uint32_t dst = sbase + SM_B + 16384u + (uint32_t)(n * 128 + ((u ^ (n & 7)) << 4));
            const __half* base = (u < 4) ? g_Wt_hi : g_Wt_lo;
            CP_ASYNC16(dst, base + (size_t)n * 256 + 32 + (u & 3) * 8);
        }
        CP_COMMIT();
    }

    float c[4][4];
#pragma unroll
    for (int n8 = 0; n8 < 4; n8++)
#pragma unroll
        for (int q = 0; q < 4; q++) c[n8][q] = 0.f;

    for (int t = 0; t < 32; t++) {
        // issue stage t+1's B
        if (t + 1 < 32) {
            int tn = t + 1;
            int chn = tn >> 3, c32n = tn & 7;
            const __half* BhiN = g_Wt_hi + (size_t)(((chn >> 1) * 256 + (chn & 1) * 128)) * 256;
            const __half* BloN = g_Wt_lo + (size_t)(((chn >> 1) * 256 + (chn & 1) * 128)) * 256;
            uint32_t bufN = sbase + SM_B + (uint32_t)((tn & 1) * 16384);
#pragma unroll
            for (int l = 0; l < 2; l++) {
                int idx = l * 512 + tid;
                int n = idx >> 3, u = idx & 7;
                uint32_t dst = bufN + (uint32_t)(n * 128 + ((u ^ (n & 7)) << 4));
                const __half* base = (u < 4) ? BhiN : BloN;
                CP_ASYNC16(dst, base + (size_t)n * 256 + c32n * 32 + (u & 3) * 8);
            }
            CP_COMMIT();
            CP_WAIT1();
        } else {
            CP_WAIT0();
        }
        __syncthreads();

        const int ch = t >> 3, c32 = t & 7;
        const int p = ch >> 1;
        const uint32_t abase = sbase + SM_A + (uint32_t)(p * 32768);
        const uint32_t bbuf = sbase + SM_B + (uint32_t)((t & 1) * 16384);

#pragma unroll
        for (int s = 0; s < 2; s++) {
            int k16 = c32 * 2 + s;                   // global k16-step 0..15
            uint32_t ah[4];
            {
                int arow = wm * 16 + am;
                uint32_t addr = abase + (uint32_t)((k16 >> 2) * 8192 + arow * 128 +
                                ((((k16 & 3) << 1 | aoff) ^ asw) << 4));
                ldsm_x4(ah[0], ah[1], ah[2], ah[3], addr);
            }
            const int vhi = (s << 1) | boff;
#pragma unroll
            for (int g = 0; g < 2; g++) {
                int brow = wn * 32 + g * 16 + bn;
                uint32_t rb = bbuf + (uint32_t)(brow * 128);
                uint32_t bh[4], bl[4];
                ldsm_x4(bh[0], bh[1], bh[2], bh[3], rb + ((vhi ^ bsw) << 4));
                ldsm_x4(bl[0], bl[1], bl[2], bl[3], rb + (((4 | vhi) ^ bsw) << 4));
                mma_fp16(c[2 * g],     ah, &bh[0]);
                mma_fp16(c[2 * g],     ah, &bl[0]);
                mma_fp16(c[2 * g + 1], ah, &bh[2]);
                mma_fp16(c[2 * g + 1], ah, &bl[2]);
            }
        }

        // chunk epilogue: park partials in smem accumulator
        if (c32 == 7) {
            const int h = ch & 1;
            const float* __restrict__ bias = p ? b1 : b0;
            float* acc = reinterpret_cast<float*>(smem + SM_ACC);
#pragma unroll
            for (int rr = 0; rr < 2; rr++) {
                int rl = wm * 16 + rr * 8 + (lane >> 2);
                int grow = m0 + rl;
                float bf = (grow < NA) ? g_cnt[p * NA + grow] : 0.f;
#pragma unroll
                for (int n8 = 0; n8 < 4; n8++) {
                    int cl = wn * 32 + n8 * 8 + (lane & 3) * 2;
                    float2 o;
                    o.x = c[n8][rr * 2 + 0] + bias[h * 128 + cl] * bf;
                    o.y = c[n8][rr * 2 + 1] + bias[h * 128 + cl + 1] * bf;
                    *reinterpret_cast<float2*>(acc + rl * 512 + p * 256 + h * 128 + cl) = o;
                }
            }
#pragma unroll
            for (int n8 = 0; n8 < 4; n8++)
#pragma unroll
                for (int q = 0; q < 4; q++) c[n8][q] = 0.f;
        }
        __syncthreads();
    }

    // ---- in-kernel finalize: warp wid handles rows wid*4 .. wid*4+3 --------
    const float* acc = reinterpret_cast<const float*>(smem + SM_ACC);
    int base = lane * 8;
    float sv[8];
    *reinterpret_cast<float4*>(&sv[0]) = *reinterpret_cast<const float4*>(sem + base);
    *reinterpret_cast<float4*>(&sv[4]) = *reinterpret_cast<const float4*>(sem + base + 4);
    float gm[8], bt[8];
    *reinterpret_cast<float4*>(&gm[0]) = *reinterpret_cast<const float4*>(gamma + base);
    *reinterpret_cast<float4*>(&gm[4]) = *reinterpret_cast<const float4*>(gamma + base + 4);
    *reinterpret_cast<float4*>(&bt[0]) = *reinterpret_cast<const float4*>(beta + base);
    *reinterpret_cast<float4*>(&bt[4]) = *reinterpret_cast<const float4*>(beta + base + 4);

    for (int i = 0; i < 4; i++) {
        int rl = wid * 4 + i;
        int n = m0 + rl;
        if (n >= NA) continue;

        const float* rowp = acc + rl * 512;
        float a0[8], a1[8];
        *reinterpret_cast<float4*>(&a0[0]) = *reinterpret_cast<const float4*>(rowp + base);
        *reinterpret_cast<float4*>(&a0[4]) = *reinterpret_cast<const float4*>(rowp + base + 4);
        *reinterpret_cast<float4*>(&a1[0]) = *reinterpret_cast<const float4*>(rowp + 256 + base);
        *reinterpret_cast<float4*>(&a1[4]) = *reinterpret_cast<const float4*>(rowp + 256 + base + 4);

        float s0 = 0.f, s1 = 0.f;
#pragma unroll
        for (int k = 0; k < 8; k++) {
            s0 += tanhf(a0[k]) * sv[k];
            s1 += tanhf(a1[k]) * sv[k];
        }
#pragma unroll
        for (int o = 16; o > 0; o >>= 1) {
            s0 += __shfl_xor_sync(0xffffffffu, s0, o);
            s1 += __shfl_xor_sync(0xffffffffu, s1, o);
        }
        float m = fmaxf(s0, s1);
        float e0 = __expf(s0 - m), e1 = __expf(s1 - m);
        float w0 = e0 / (e0 + e1);
        float w1 = 1.0f - w0;

        float f[8];
        float sum = 0.f, sq = 0.f;
#pragma unroll
        for (int k = 0; k < 8; k++) {
            f[k] = fmaxf(w0 * a0[k] + w1 * a1[k], 0.f);
            sum += f[k];
            sq  += f[k] * f[k];
        }
#pragma unroll
        for (int o = 16; o > 0; o >>= 1) {
            sum += __shfl_xor_sync(0xffffffffu, sum, o);
            sq  += __shfl_xor_sync(0xffffffffu, sq, o);
        }
        float mu  = sum * (1.0f / 256.0f);
        float var = sq * (1.0f / 256.0f) - mu * mu;
        float rstd = rsqrtf(var + LN_EPS);

        float o8[8];
#pragma unroll
        for (int k = 0; k < 8; k++)
            o8[k] = (f[k] - mu) * rstd * gm[k] + bt[k];

        float* op = outA + (size_t)n * 256 + base;
        *reinterpret_cast<float4*>(op)     = *reinterpret_cast<float4*>(&o8[0]);
        *reinterpret_cast<float4*>(op + 4) = *reinterpret_cast<float4*>(&o8[4]);
    }
}

// ---------------- launch ----------------------------------------------------
extern "C" void kernel_launch(void* const* d_in, const int* in_sizes, int n_in,
                              void* d_out, int out_size)
{
    const float* x_B  = (const float*)d_in[1];
    const int*   ei0  = (const int*)d_in[2];
    const int*   ei1  = (const int*)d_in[3];
    const float* W0   = (const float*)d_in[4];
    const float* b0   = (const float*)d_in[5];
    const float* W1   = (const float*)d_in[6];
    const float* b1   = (const float*)d_in[7];
    const float* sem  = (const float*)d_in[8];
    const float* gam  = (const float*)d_in[9];
    const float* bet  = (const float*)d_in[10];

    float* outA = (float*)d_out;
    float* outB = outA + (size_t)NA * OUT_DIM;

    cudaFuncSetAttribute(fused_kernel,
                         cudaFuncAttributeMaxDynamicSharedMemorySize, FSM_TOTAL);

    zero_hist_kernel<<<(NBIN / 4 + 255) / 256, 256>>>();
    splitW_kernel<<<512, 256>>>(W0, W1);

    hist_kernel<<<(2 * NE + 255) / 256, 256>>>(ei0, ei1);
    scanA_kernel<<<NBLK, SCAN_B>>>();
    scanB_kernel<<<1, SCAN_B>>>();
    scanC_kernel<<<NBLK, SCAN_B>>>();
    fill_kernel<<<(2 * NE + 255) / 256, 256>>>(ei0, ei1);

    agg_kernel<<<(NBIN * 32 + 255) / 256, 256>>>(x_B);

    fused_kernel<<<MT + ZB_BLOCKS, 512, FSM_TOTAL>>>(b0, b1, sem, gam, bet,
                                                     outA, outB);
}

// round 11
// speedup vs baseline: 1.2129x; 1.2129x over previous
#include <cuda_runtime.h>
#include <cuda_fp16.h>
#include <cstdint>

#define NA 100000
#define NB 100000
#define IN_DIM 256
#define OUT_DIM 256
#define NE 320000
#define LN_EPS 1e-5f

#define NBIN (2 * NA)
#define SCAN_B 512
#define NBLK ((NBIN + SCAN_B - 1) / SCAN_B)   // 391

// ---------------- scratch (device globals; no allocation allowed) -----------
__device__ float g_agg[(size_t)2 * NA * 256];        // per-path mean+bias
__device__ float g_cnt[NBIN];                        // 1.0 if deg>0 else 0.0
__device__ __half g_Sh[(size_t)NBIN * 256];          // per-bin MEAN, fp16
__device__ __half g_Wt_hi[512 * 256];                // Wcat^T [n][k], fp16 hi
__device__ __half g_Wt_lo[512 * 256];                // fp16 lo residual
__device__ int g_hist[NBIN];
__device__ int g_rowptr[NBIN];
__device__ int g_cursor[NBIN];
__device__ int g_elist[2 * NE];
__device__ int g_blocksums[SCAN_B];
__device__ int g_blockoff[SCAN_B];

// ---------------- helpers ----------------------------------------------------
__device__ __forceinline__ uint32_t smem_u32(const void* p) {
    uint32_t a;
    asm("{ .reg .u64 t; cvta.to.shared.u64 t, %1; cvt.u32.u64 %0, t; }" : "=r"(a) : "l"(p));
    return a;
}
__device__ __forceinline__ void ldsm_x4(uint32_t& r0, uint32_t& r1, uint32_t& r2,
                                        uint32_t& r3, uint32_t addr) {
    asm volatile("ldmatrix.sync.aligned.m8n8.x4.shared.b16 {%0,%1,%2,%3}, [%4];"
                 : "=r"(r0), "=r"(r1), "=r"(r2), "=r"(r3) : "r"(addr));
}
__device__ __forceinline__ void mma_fp16(float* c, const uint32_t* a, const uint32_t* b) {
    asm volatile("mma.sync.aligned.m16n8k16.row.col.f32.f16.f16.f32 "
                 "{%0,%1,%2,%3}, {%4,%5,%6,%7}, {%8,%9}, {%0,%1,%2,%3};"
                 : "+f"(c[0]), "+f"(c[1]), "+f"(c[2]), "+f"(c[3])
                 : "r"(a[0]), "r"(a[1]), "r"(a[2]), "r"(a[3]), "r"(b[0]), "r"(b[1]));
}
#define CP_ASYNC16(sm, gp) \
    asm volatile("cp.async.cg.shared.global [%0], [%1], 16;" \
                 :: "r"(sm), "l"(gp) : "memory")
#define CP_ASYNC16Z(sm, gp, sz) \
    asm volatile("cp.async.cg.shared.global [%0], [%1], 16, %2;" \
                 :: "r"(sm), "l"(gp), "r"(sz) : "memory")
#define CP_COMMIT() asm volatile("cp.async.commit_group;" ::: "memory")
#define CP_WAIT0()  asm volatile("cp.async.wait_group 0;" ::: "memory")
#define CP_WAIT1()  asm volatile("cp.async.wait_group 1;" ::: "memory")

// ---------------- zero hist ---------------------------------------------------
__global__ __launch_bounds__(256) void zero_hist_kernel() {
    size_t i = (size_t)blockIdx.x * 256 + threadIdx.x;
    if (i < NBIN / 4)
        reinterpret_cast<int4*>(g_hist)[i] = make_int4(0, 0, 0, 0);
}

// ---------------- W split/transpose prep ------------------------------------
__global__ __launch_bounds__(256) void splitW_kernel(const float* __restrict__ W0,
                                                     const float* __restrict__ W1) {
    int n = blockIdx.x;
    int k = threadIdx.x;
    float w = (n < 256) ? W0[k * 256 + n] : W1[k * 256 + (n - 256)];
    __half h = __float2half_rn(w);
    float r = w - __half2float(h);
    g_Wt_hi[n * 256 + k] = h;
    g_Wt_lo[n * 256 + k] = __float2half_rn(r);
}

// ---------------- CSR build --------------------------------------------------
__global__ __launch_bounds__(256) void hist_kernel(
    const int* __restrict__ ei0, const int* __restrict__ ei1)
{
    int i = blockIdx.x * 256 + threadIdx.x;
    if (i >= 2 * NE) return;
    int p = (i >= NE) ? 1 : 0;
    int e = i - p * NE;
    const int* __restrict__ ei = p ? ei1 : ei0;
    int dst = ei[e + NE];
    atomicAdd(&g_hist[p * NA + dst], 1);
}

__global__ __launch_bounds__(SCAN_B) void scanA_kernel() {
    __shared__ int sh[SCAN_B];
    int i = blockIdx.x * SCAN_B + threadIdx.x;
    sh[threadIdx.x] = (i < NBIN) ? g_hist[i] : 0;
    __syncthreads();
    for (int d = SCAN_B / 2; d > 0; d >>= 1) {
        if (threadIdx.x < d) sh[threadIdx.x] += sh[threadIdx.x + d];
        __syncthreads();
    }
    if (threadIdx.x == 0) g_blocksums[blockIdx.x] = sh[0];
}

__global__ __launch_bounds__(SCAN_B) void scanB_kernel() {
    __shared__ int sh[SCAN_B];
    int tid = threadIdx.x;
    int v = (tid < NBLK) ? g_blocksums[tid] : 0;
    sh[tid] = v;
    __syncthreads();
    for (int d = 1; d < SCAN_B; d <<= 1) {
        int t = (tid >= d) ? sh[tid - d] : 0;
        __syncthreads();
        sh[tid] += t;
        __syncthreads();
    }
    if (tid < NBLK) g_blockoff[tid] = sh[tid] - v;
}

__global__ __launch_bounds__(SCAN_B) void scanC_kernel() {
    __shared__ int sh[SCAN_B];
    int tid = threadIdx.x;
    int i = blockIdx.x * SCAN_B + tid;
    int v = (i < NBIN) ? g_hist[i] : 0;
    sh[tid] = v;
    __syncthreads();
    for (int d = 1; d < SCAN_B; d <<= 1) {
        int t = (tid >= d) ? sh[tid - d] : 0;
        __syncthreads();
        sh[tid] += t;
        __syncthreads();
    }
    if (i < NBIN) {
        int excl = sh[tid] - v + g_blockoff[blockIdx.x];
        g_rowptr[i] = excl;
        g_cursor[i] = excl;
        g_cnt[i] = (v > 0) ? 1.0f : 0.0f;
    }
}

__global__ __launch_bounds__(256) void fill_kernel(
    const int* __restrict__ ei0, const int* __restrict__ ei1)
{
    int i = blockIdx.x * 256 + threadIdx.x;
    if (i >= 2 * NE) return;
    int p = (i >= NE) ? 1 : 0;
    int e = i - p * NE;
    const int* __restrict__ ei = p ? ei1 : ei0;
    int src = ei[e];
    int dst = ei[e + NE];
    int pos = atomicAdd(&g_cursor[p * NA + dst], 1);
    g_elist[pos] = src;
}

// ---------------- aggregate: warp per bin; chunked MLP-8 gather --------------
__global__ __launch_bounds__(256) void agg_kernel(const float* __restrict__ xB) {
    int w = (blockIdx.x * 256 + threadIdx.x) >> 5;
    int lane = threadIdx.x & 31;
    if (w >= NBIN) return;
    int start = g_rowptr[w];
    int deg = g_hist[w];

    float a[8] = {0.f, 0.f, 0.f, 0.f, 0.f, 0.f, 0.f, 0.f};

    for (int j = 0; j < deg; j += 8) {
        int m = deg - j;
        if (m > 8) m = 8;
        int idx[8];
#pragma unroll
        for (int k = 0; k < 8; k++)
            idx[k] = (k < m) ? __ldg(&g_elist[start + j + k]) : 0;
        float4 va[8], vb[8];
#pragma unroll
        for (int k = 0; k < 8; k++) {
            if (k < m) {
                const float4* r = reinterpret_cast<const float4*>(
                    xB + (size_t)idx[k] * 256) + lane * 2;
                va[k] = r[0];
                vb[k] = r[1];
            } else {
                va[k] = make_float4(0.f, 0.f, 0.f, 0.f);
                vb[k] = make_float4(0.f, 0.f, 0.f, 0.f);
            }
        }
#pragma unroll
        for (int k = 0; k < 8; k++) {
            a[0] += va[k].x; a[1] += va[k].y; a[2] += va[k].z; a[3] += va[k].w;
            a[4] += vb[k].x; a[5] += vb[k].y; a[6] += vb[k].z; a[7] += vb[k].w;
        }
    }

    float inv = (deg > 0) ? 1.0f / (float)deg : 0.0f;
    __half2 h0 = __floats2half2_rn(a[0] * inv, a[1] * inv);
    __half2 h1 = __floats2half2_rn(a[2] * inv, a[3] * inv);
    __half2 h2 = __floats2half2_rn(a[4] * inv, a[5] * inv);
    __half2 h3 = __floats2half2_rn(a[6] * inv, a[7] * inv);
    uint4 hv;
    hv.x = *reinterpret_cast<uint32_t*>(&h0);
    hv.y = *reinterpret_cast<uint32_t*>(&h1);
    hv.z = *reinterpret_cast<uint32_t*>(&h2);
    hv.w = *reinterpret_cast<uint32_t*>(&h3);
    *reinterpret_cast<uint4*>(g_Sh + (size_t)w * 256 + lane * 8) = hv;
}

// ---------------- HMMA GEMM: A-resident, both col-halves per CTA -------------
// grid (2, 782): bx = p, by = m-tile (128 rows). A (128 x 256 k fp16, 64KB)
// loads once; B streams as 16 double-buffered 16KB (h, kc32) chunks.
#define GA_SMEM 0
#define GB_SMEM 65536
#define GSM_TOTAL 98304

__global__ __launch_bounds__(256, 2) void gemm_mma_kernel(
    const float* __restrict__ b0, const float* __restrict__ b1)
{
    extern __shared__ char smem[];
    const uint32_t sbase = smem_u32(smem);
    const int tid = threadIdx.x, lane = tid & 31, wid = tid >> 5;
    const int wm = wid & 3;
    const int wn = wid >> 2;
    const int p = blockIdx.x;
    const int m0 = blockIdx.y * 128;

    const __half* __restrict__ Ah  = g_Sh + (size_t)p * NA * 256;
    const __half* __restrict__ Bhi = g_Wt_hi + (size_t)p * 256 * 256;
    const __half* __restrict__ Blo = g_Wt_lo + (size_t)p * 256 * 256;

    const int am = lane & 15;
    const int aoff = lane >> 4;
    const int asw = am & 7;
    const int bn = (lane & 7) | ((lane & 16) >> 1);
    const int boff = (lane >> 3) & 1;
    const int bsw = bn & 7;

    // ---- issue A (full K) + B stage 0 as one group; then B stage 1 ---------
#pragma unroll
    for (int l = 0; l < 16; l++) {
        int idx = l * 256 + tid;                 // 0..4095 16B units
        int c64 = idx >> 10;
        int rem = idx & 1023;
        int r = rem >> 3, u = rem & 7;
        int grow = m0 + r;
        int ok = (grow < NA) ? 16 : 0;
        int grc = (grow < NA) ? grow : (NA - 1);
        uint32_t dst = sbase + GA_SMEM + (uint32_t)(c64 * 16384 + r * 128 +
                        ((u ^ (r & 7)) << 4));
        const __half* src = Ah + (size_t)grc * 256 + c64 * 64 + u * 8;
        CP_ASYNC16Z(dst, src, ok);
    }
    // B stage helper (inline twice + in loop)
#define ISSUE_B(stage) do { \
        int _h = (stage) >> 3, _kc = (stage) & 7; \
        uint32_t _buf = sbase + GB_SMEM + (uint32_t)(((stage) & 1) * 16384); \
        _Pragma("unroll") \
        for (int _l = 0; _l < 4; _l++) { \
            int _idx = _l * 256 + tid; \
            int _n = _idx >> 3, _u = _idx & 7; \
            uint32_t _dst = _buf + (uint32_t)(_n * 128 + ((_u ^ (_n & 7)) << 4)); \
            const __half* _base = (_u < 4) ? Bhi : Blo; \
            const __half* _src = _base + (size_t)(_h * 128 + _n) * 256 + _kc * 32 + (_u & 3) * 8; \
            CP_ASYNC16(_dst, _src); \
        } \
        CP_COMMIT(); \
    } while (0)

    ISSUE_B(0);        // group 1 = A + B0
    ISSUE_B(1);        // group 2 = B1

    float c[2][8][4];
#pragma unroll
    for (int mt = 0; mt < 2; mt++)
#pragma unroll
        for (int n8 = 0; n8 < 8; n8++)
#pragma unroll
            for (int q = 0; q < 4; q++) c[mt][n8][q] = 0.f;

    for (int t = 0; t < 16; t++) {
        if (t < 15) { CP_WAIT1(); } else { CP_WAIT0(); }
        __syncthreads();

        const int kc32 = t & 7;
        const uint32_t bbuf = sbase + GB_SMEM + (uint32_t)((t & 1) * 16384);

#pragma unroll
        for (int s = 0; s < 2; s++) {
            const int k16 = kc32 * 2 + s;
            uint32_t ah[2][4];
#pragma unroll
            for (int mt = 0; mt < 2; mt++) {
                int arow = wm * 32 + mt * 16 + am;
                uint32_t addr = sbase + GA_SMEM + (uint32_t)((k16 >> 2) * 16384 +
                                arow * 128 + (((((k16 & 3) << 1) | aoff) ^ asw) << 4));
                ldsm_x4(ah[mt][0], ah[mt][1], ah[mt][2], ah[mt][3], addr);
            }
            const int vhi = (s << 1) | boff;
#pragma unroll
            for (int g = 0; g < 4; g++) {
                int brow = wn * 64 + g * 16 + bn;
                uint32_t rb = bbuf + (uint32_t)(brow * 128);
                uint32_t bh[4], bl[4];
                ldsm_x4(bh[0], bh[1], bh[2], bh[3], rb + ((vhi ^ bsw) << 4));
                ldsm_x4(bl[0], bl[1], bl[2], bl[3], rb + (((4 | vhi) ^ bsw) << 4));
#pragma unroll
                for (int mt = 0; mt < 2; mt++) {
                    mma_fp16(c[mt][2 * g],     ah[mt], &bh[0]);
                    mma_fp16(c[mt][2 * g],     ah[mt], &bl[0]);
                    mma_fp16(c[mt][2 * g + 1], ah[mt], &bh[2]);
                    mma_fp16(c[mt][2 * g + 1], ah[mt], &bl[2]);
                }
            }
        }

        // half-boundary epilogue: write this h's 128 cols, reset accums
        if (kc32 == 7) {
            const int h = t >> 3;
            const float* __restrict__ bias = p ? b1 : b0;
            float* __restrict__ dst = g_agg + (size_t)p * NA * 256;
#pragma unroll
            for (int mt = 0; mt < 2; mt++) {
#pragma unroll
                for (int rr = 0; rr < 2; rr++) {
                    int row = m0 + wm * 32 + mt * 16 + rr * 8 + (lane >> 2);
                    if (row >= NA) continue;
                    float bf = g_cnt[p * NA + row];
                    float* orow = dst + (size_t)row * 256;
#pragma unroll
                    for (int n8 = 0; n8 < 8; n8++) {
                        int col = h * 128 + wn * 64 + n8 * 8 + (lane & 3) * 2;
                        float2 o;
                        o.x = c[mt][n8][rr * 2 + 0] + bias[col] * bf;
                        o.y = c[mt][n8][rr * 2 + 1] + bias[col + 1] * bf;
                        *reinterpret_cast<float2*>(orow + col) = o;
                    }
                }
            }
#pragma unroll
            for (int mt = 0; mt < 2; mt++)
#pragma unroll
                for (int n8 = 0; n8 < 8; n8++)
#pragma unroll
                    for (int q = 0; q < 4; q++) c[mt][n8][q] = 0.f;
        }
        __syncthreads();
        if (t + 2 < 16) ISSUE_B(t + 2);
    }
#undef ISSUE_B
}

// ---------------- finalize + outB zeroing ------------------------------------
#define FIN_BLOCKS ((NA * 32 + 255) / 256)                    // 12500
#define ZB_BLOCKS  ((int)(((size_t)NB * OUT_DIM / 4 + 255) / 256))  // 25000

__global__ __launch_bounds__(256) void finalize_kernel(
    const float* __restrict__ sem, const float* __restrict__ gamma,
    const float* __restrict__ beta, float* __restrict__ outA,
    float* __restrict__ outB)
{
    if (blockIdx.x >= FIN_BLOCKS) {
        size_t i = (size_t)(blockIdx.x - FIN_BLOCKS) * 256 + threadIdx.x;
        if (i < (size_t)NB * OUT_DIM / 4)
            reinterpret_cast<float4*>(outB)[i] = make_float4(0.f, 0.f, 0.f, 0.f);
        return;
    }
    int n = (blockIdx.x * 256 + threadIdx.x) >> 5;
    int lane = threadIdx.x & 31;
    if (n >= NA) return;
    int base = lane * 8;

    const float* a0p = g_agg + (size_t)n * 256;
    const float* a1p = g_agg + ((size_t)NA + n) * 256;

    float a0[8], a1[8], sv[8];
    *reinterpret_cast<float4*>(&a0[0]) = *reinterpret_cast<const float4*>(a0p + base);
    *reinterpret_cast<float4*>(&a0[4]) = *reinterpret_cast<const float4*>(a0p + base + 4);
    *reinterpret_cast<float4*>(&a1[0]) = *reinterpret_cast<const float4*>(a1p + base);
    *reinterpret_cast<float4*>(&a1[4]) = *reinterpret_cast<const float4*>(a1p + base + 4);
    *reinterpret_cast<float4*>(&sv[0]) = *reinterpret_cast<const float4*>(sem + base);
    *reinterpret_cast<float4*>(&sv[4]) = *reinterpret_cast<const float4*>(sem + base + 4);

    float s0 = 0.f, s1 = 0.f;
#pragma unroll
    for (int i = 0; i < 8; i++) {
        s0 += tanhf(a0[i]) * sv[i];
        s1 += tanhf(a1[i]) * sv[i];
    }
#pragma unroll
    for (int o = 16; o > 0; o >>= 1) {
        s0 += __shfl_xor_sync(0xffffffffu, s0, o);
        s1 += __shfl_xor_sync(0xffffffffu, s1, o);
    }
    float m = fmaxf(s0, s1);
    float e0 = __expf(s0 - m), e1 = __expf(s1 - m);
    float w0 = e0 / (e0 + e1);
    float w1 = 1.0f - w0;

    float f[8];
    float sum = 0.f, sq = 0.f;
#pragma unroll
    for (int i = 0; i < 8; i++) {
        f[i] = fmaxf(w0 * a0[i] + w1 * a1[i], 0.f);
        sum += f[i];
        sq  += f[i] * f[i];
    }
#pragma unroll
    for (int o = 16; o > 0; o >>= 1) {
        sum += __shfl_xor_sync(0xffffffffu, sum, o);
        sq  += __shfl_xor_sync(0xffffffffu, sq, o);
    }
    float mu  = sum * (1.0f / 256.0f);
    float var = sq * (1.0f / 256.0f) - mu * mu;
    float rstd = rsqrtf(var + LN_EPS);

    float gm[8], bt[8];
    *reinterpret_cast<float4*>(&gm[0]) = *reinterpret_cast<const float4*>(gamma + base);
    *reinterpret_cast<float4*>(&gm[4]) = *reinterpret_cast<const float4*>(gamma + base + 4);
    *reinterpret_cast<float4*>(&bt[0]) = *reinterpret_cast<const float4*>(beta + base);
    *reinterpret_cast<float4*>(&bt[4]) = *reinterpret_cast<const float4*>(beta + base + 4);

    float o8[8];
#pragma unroll
    for (int i = 0; i < 8; i++)
        o8[i] = (f[i] - mu) * rstd * gm[i] + bt[i];

    float* op = outA + (size_t)n * 256 + base;
    *reinterpret_cast<float4*>(op)     = *reinterpret_cast<float4*>(&o8[0]);
    *reinterpret_cast<float4*>(op + 4) = *reinterpret_cast<float4*>(&o8[4]);
}

// ---------------- launch ----------------------------------------------------
extern "C" void kernel_launch(void* const* d_in, const int* in_sizes, int n_in,
                              void* d_out, int out_size)
{
    const float* x_B  = (const float*)d_in[1];
    const int*   ei0  = (const int*)d_in[2];
    const int*   ei1  = (const int*)d_in[3];
    const float* W0   = (const float*)d_in[4];
    const float* b0   = (const float*)d_in[5];
    const float* W1   = (const float*)d_in[6];
    const float* b1   = (const float*)d_in[7];
    const float* sem  = (const float*)d_in[8];
    const float* gam  = (const float*)d_in[9];
    const float* bet  = (const float*)d_in[10];

    float* outA = (float*)d_out;
    float* outB = outA + (size_t)NA * OUT_DIM;

    cudaFuncSetAttribute(gemm_mma_kernel,
                         cudaFuncAttributeMaxDynamicSharedMemorySize, GSM_TOTAL);

    zero_hist_kernel<<<(NBIN / 4 + 255) / 256, 256>>>();
    splitW_kernel<<<512, 256>>>(W0, W1);

    hist_kernel<<<(2 * NE + 255) / 256, 256>>>(ei0, ei1);
    scanA_kernel<<<NBLK, SCAN_B>>>();
    scanB_kernel<<<1, SCAN_B>>>();
    scanC_kernel<<<NBLK, SCAN_B>>>();
    fill_kernel<<<(2 * NE + 255) / 256, 256>>>(ei0, ei1);

    agg_kernel<<<(NBIN * 32 + 255) / 256, 256>>>(x_B);

    {
        dim3 grid(2, (NA + 127) / 128);
        gemm_mma_kernel<<<grid, 256, GSM_TOTAL>>>(b0, b1);
    }

    finalize_kernel<<<FIN_BLOCKS + ZB_BLOCKS, 256>>>(sem, gam, bet, outA, outB);
}

// round 12
// speedup vs baseline: 1.3199x; 1.0882x over previous
#include <cuda_runtime.h>
#include <cuda_fp16.h>
#include <cstdint>

#define NA 100000
#define NB 100000
#define IN_DIM 256
#define OUT_DIM 256
#define NE 320000
#define LN_EPS 1e-5f

#define NBIN (2 * NA)
#define SCAN_B 512
#define NBLK ((NBIN + SCAN_B - 1) / SCAN_B)   // 391

// ---------------- scratch (device globals; no allocation allowed) -----------
__device__ __half g_aggh[(size_t)2 * NA * 256];      // per-path mean+bias (fp16)
__device__ float g_cnt[NBIN];                        // 1.0 if deg>0 else 0.0
__device__ __half g_Sh[(size_t)NBIN * 256];          // per-bin MEAN, fp16
__device__ __half g_Wt_hi[512 * 256];                // Wcat^T [n][k], fp16 hi
__device__ __half g_Wt_lo[512 * 256];                // fp16 lo residual
__device__ int g_hist[NBIN];
__device__ int g_rowptr[NBIN];
__device__ int g_cursor[NBIN];
__device__ int g_elist[2 * NE];
__device__ int g_blocksums[SCAN_B];
__device__ int g_blockoff[SCAN_B];

// ---------------- helpers ----------------------------------------------------
__device__ __forceinline__ uint32_t smem_u32(const void* p) {
    uint32_t a;
    asm("{ .reg .u64 t; cvta.to.shared.u64 t, %1; cvt.u32.u64 %0, t; }" : "=r"(a) : "l"(p));
    return a;
}
__device__ __forceinline__ void ldsm_x4(uint32_t& r0, uint32_t& r1, uint32_t& r2,
                                        uint32_t& r3, uint32_t addr) {
    asm volatile("ldmatrix.sync.aligned.m8n8.x4.shared.b16 {%0,%1,%2,%3}, [%4];"
                 : "=r"(r0), "=r"(r1), "=r"(r2), "=r"(r3) : "r"(addr));
}
__device__ __forceinline__ void mma_fp16(float* c, const uint32_t* a, const uint32_t* b) {
    asm volatile("mma.sync.aligned.m16n8k16.row.col.f32.f16.f16.f32 "
                 "{%0,%1,%2,%3}, {%4,%5,%6,%7}, {%8,%9}, {%0,%1,%2,%3};"
                 : "+f"(c[0]), "+f"(c[1]), "+f"(c[2]), "+f"(c[3])
                 : "r"(a[0]), "r"(a[1]), "r"(a[2]), "r"(a[3]), "r"(b[0]), "r"(b[1]));
}
#define CP_ASYNC16(sm, gp) \
    asm volatile("cp.async.cg.shared.global [%0], [%1], 16;" \
                 :: "r"(sm), "l"(gp) : "memory")
#define CP_ASYNC16Z(sm, gp, sz) \
    asm volatile("cp.async.cg.shared.global [%0], [%1], 16, %2;" \
                 :: "r"(sm), "l"(gp), "r"(sz) : "memory")
#define CP_COMMIT() asm volatile("cp.async.commit_group;" ::: "memory")
#define CP_WAIT0()  asm volatile("cp.async.wait_group 0;" ::: "memory")
#define CP_WAIT1()  asm volatile("cp.async.wait_group 1;" ::: "memory")

// ---------------- zero hist ---------------------------------------------------
__global__ __launch_bounds__(256) void zero_hist_kernel() {
    size_t i = (size_t)blockIdx.x * 256 + threadIdx.x;
    if (i < NBIN / 4)
        reinterpret_cast<int4*>(g_hist)[i] = make_int4(0, 0, 0, 0);
}

// ---------------- W split/transpose prep ------------------------------------
__global__ __launch_bounds__(256) void splitW_kernel(const float* __restrict__ W0,
                                                     const float* __restrict__ W1) {
    int n = blockIdx.x;
    int k = threadIdx.x;
    float w = (n < 256) ? W0[k * 256 + n] : W1[k * 256 + (n - 256)];
    __half h = __float2half_rn(w);
    float r = w - __half2float(h);
    g_Wt_hi[n * 256 + k] = h;
    g_Wt_lo[n * 256 + k] = __float2half_rn(r);
}

// ---------------- CSR build --------------------------------------------------
__global__ __launch_bounds__(256) void hist_kernel(
    const int* __restrict__ ei0, const int* __restrict__ ei1)
{
    int i = blockIdx.x * 256 + threadIdx.x;
    if (i >= 2 * NE) return;
    int p = (i >= NE) ? 1 : 0;
    int e = i - p * NE;
    const int* __restrict__ ei = p ? ei1 : ei0;
    int dst = ei[e + NE];
    atomicAdd(&g_hist[p * NA + dst], 1);
}

__global__ __launch_bounds__(SCAN_B) void scanA_kernel() {
    __shared__ int sh[SCAN_B];
    int i = blockIdx.x * SCAN_B + threadIdx.x;
    sh[threadIdx.x] = (i < NBIN) ? g_hist[i] : 0;
    __syncthreads();
    for (int d = SCAN_B / 2; d > 0; d >>= 1) {
        if (threadIdx.x < d) sh[threadIdx.x] += sh[threadIdx.x + d];
        __syncthreads();
    }
    if (threadIdx.x == 0) g_blocksums[blockIdx.x] = sh[0];
}

__global__ __launch_bounds__(SCAN_B) void scanB_kernel() {
    __shared__ int sh[SCAN_B];
    int tid = threadIdx.x;
    int v = (tid < NBLK) ? g_blocksums[tid] : 0;
    sh[tid] = v;
    __syncthreads();
    for (int d = 1; d < SCAN_B; d <<= 1) {
        int t = (tid >= d) ? sh[tid - d] : 0;
        __syncthreads();
        sh[tid] += t;
        __syncthreads();
    }
    if (tid < NBLK) g_blockoff[tid] = sh[tid] - v;
}

__global__ __launch_bounds__(SCAN_B) void scanC_kernel() {
    __shared__ int sh[SCAN_B];
    int tid = threadIdx.x;
    int i = blockIdx.x * SCAN_B + tid;
    int v = (i < NBIN) ? g_hist[i] : 0;
    sh[tid] = v;
    __syncthreads();
    for (int d = 1; d < SCAN_B; d <<= 1) {
        int t = (tid >= d) ? sh[tid - d] : 0;
        __syncthreads();
        sh[tid] += t;
        __syncthreads();
    }
    if (i < NBIN) {
        int excl = sh[tid] - v + g_blockoff[blockIdx.x];
        g_rowptr[i] = excl;
        g_cursor[i] = excl;
        g_cnt[i] = (v > 0) ? 1.0f : 0.0f;
    }
}

__global__ __launch_bounds__(256) void fill_kernel(
    const int* __restrict__ ei0, const int* __restrict__ ei1)
{
    int i = blockIdx.x * 256 + threadIdx.x;
    if (i >= 2 * NE) return;
    int p = (i >= NE) ? 1 : 0;
    int e = i - p * NE;
    const int* __restrict__ ei = p ? ei1 : ei0;
    int src = ei[e];
    int dst = ei[e + NE];
    int pos = atomicAdd(&g_cursor[p * NA + dst], 1);
    g_elist[pos] = src;
}

// ---------------- aggregate: warp per bin; mean -> fp16 ----------------------
__global__ __launch_bounds__(256) void agg_kernel(const float* __restrict__ xB) {
    int w = (blockIdx.x * 256 + threadIdx.x) >> 5;
    int lane = threadIdx.x & 31;
    if (w >= NBIN) return;
    int start = g_rowptr[w];
    int deg = g_hist[w];

    float a[8] = {0.f, 0.f, 0.f, 0.f, 0.f, 0.f, 0.f, 0.f};

    int j = 0;
    for (; j + 4 <= deg; j += 4) {
        int s0 = __ldg(&g_elist[start + j]);
        int s1 = __ldg(&g_elist[start + j + 1]);
        int s2 = __ldg(&g_elist[start + j + 2]);
        int s3 = __ldg(&g_elist[start + j + 3]);
        const float4* r0 = reinterpret_cast<const float4*>(xB + (size_t)s0 * 256) + lane * 2;
        const float4* r1 = reinterpret_cast<const float4*>(xB + (size_t)s1 * 256) + lane * 2;
        const float4* r2 = reinterpret_cast<const float4*>(xB + (size_t)s2 * 256) + lane * 2;
        const float4* r3 = reinterpret_cast<const float4*>(xB + (size_t)s3 * 256) + lane * 2;
        float4 v0a = r0[0], v0b = r0[1];
        float4 v1a = r1[0], v1b = r1[1];
        float4 v2a = r2[0], v2b = r2[1];
        float4 v3a = r3[0], v3b = r3[1];
        a[0] += v0a.x + v1a.x + v2a.x + v3a.x;
        a[1] += v0a.y + v1a.y + v2a.y + v3a.y;
        a[2] += v0a.z + v1a.z + v2a.z + v3a.z;
        a[3] += v0a.w + v1a.w + v2a.w + v3a.w;
        a[4] += v0b.x + v1b.x + v2b.x + v3b.x;
        a[5] += v0b.y + v1b.y + v2b.y + v3b.y;
        a[6] += v0b.z + v1b.z + v2b.z + v3b.z;
        a[7] += v0b.w + v1b.w + v2b.w + v3b.w;
    }
    for (; j < deg; j++) {
        int src = __ldg(&g_elist[start + j]);
        const float4* r4 = reinterpret_cast<const float4*>(xB + (size_t)src * 256) + lane * 2;
        float4 v0 = r4[0], v1 = r4[1];
        a[0] += v0.x; a[1] += v0.y; a[2] += v0.z; a[3] += v0.w;
        a[4] += v1.x; a[5] += v1.y; a[6] += v1.z; a[7] += v1.w;
    }

    float inv = (deg > 0) ? 1.0f / (float)deg : 0.0f;
    __half2 h0 = __floats2half2_rn(a[0] * inv, a[1] * inv);
    __half2 h1 = __floats2half2_rn(a[2] * inv, a[3] * inv);
    __half2 h2 = __floats2half2_rn(a[4] * inv, a[5] * inv);
    __half2 h3 = __floats2half2_rn(a[6] * inv, a[7] * inv);
    uint4 hv;
    hv.x = *reinterpret_cast<uint32_t*>(&h0);
    hv.y = *reinterpret_cast<uint32_t*>(&h1);
    hv.z = *reinterpret_cast<uint32_t*>(&h2);
    hv.w = *reinterpret_cast<uint32_t*>(&h3);
    *reinterpret_cast<uint4*>(g_Sh + (size_t)w * 256 + lane * 8) = hv;
}

// ---------------- HMMA GEMM: agg = mean @ W + b --------------------------------
// grid (4, 782): bx = p*2+h, by = m-tile. A fp16 (quantized), B fp16 hi+lo.
// K-chunk 64: stage = [A 16KB | B1 16KB | B2 16KB] = 48KB; 2 stages = 96KB.
#define GBUF 49152
#define GSM_TOTAL (2 * GBUF)

__device__ __forceinline__ void gemm_issue(
    uint32_t sb, int tid, int m0,
    const __half* __restrict__ Ah,
    const __half* __restrict__ Bhi, const __half* __restrict__ Blo,
    int kc)
{
    // A: 128 rows x 64 k fp16 = 1024 x 16B units
#pragma unroll
    for (int l = 0; l < 4; l++) {
        int idx = l * 256 + tid;
        int r = idx >> 3, u = idx & 7;
        int grow = m0 + r;
        int ok = (grow < NA) ? 16 : 0;
        int grc = (grow < NA) ? grow : (NA - 1);
        uint32_t dst = sb + (uint32_t)(r * 128 + ((u ^ (r & 7)) << 4));
        const __half* src = Ah + (size_t)grc * 256 + kc * 64 + u * 8;
        CP_ASYNC16Z(dst, src, ok);
    }
    // B: 2 sub-tiles (k 0-31, 32-63), each 128 rows x [hi 64B | lo 64B]
#pragma unroll
    for (int l = 0; l < 8; l++) {
        int idx = l * 256 + tid;
        int sub = idx >> 10, rem = idx & 1023;
        int n = rem >> 3, u = rem & 7;
        uint32_t dst = sb + 16384u + (uint32_t)(sub * 16384 + n * 128 + ((u ^ (n & 7)) << 4));
        const __half* base = (u < 4) ? Bhi : Blo;
        const __half* src = base + (size_t)n * 256 + kc * 64 + sub * 32 + (u & 3) * 8;
        CP_ASYNC16(dst, src);
    }
    CP_COMMIT();
}

__global__ __launch_bounds__(256, 2) void gemm_mma_kernel(
    const float* __restrict__ b0, const float* __restrict__ b1)
{
    extern __shared__ char smem[];
    const uint32_t sbase = smem_u32(smem);
    const int tid = threadIdx.x, lane = tid & 31, wid = tid >> 5;
    const int wm = wid & 3;
    const int wn = wid >> 2;
    const int p = blockIdx.x >> 1, h = blockIdx.x & 1;
    const int m0 = blockIdx.y * 128;

    const __half* __restrict__ Ah  = g_Sh + (size_t)p * NA * 256;
    const __half* __restrict__ Bhi = g_Wt_hi + (size_t)(p * 256 + h * 128) * 256;
    const __half* __restrict__ Blo = g_Wt_lo + (size_t)(p * 256 + h * 128) * 256;

    float c[2][8][4];
#pragma unroll
    for (int mt = 0; mt < 2; mt++)
#pragma unroll
        for (int n8 = 0; n8 < 8; n8++)
#pragma unroll
            for (int q = 0; q < 4; q++) c[mt][n8][q] = 0.f;

    const int am = lane & 15;
    const int aoff = lane >> 4;
    const int asw = am & 7;
    const int bn = (lane & 7) | ((lane & 16) >> 1);
    const int boff = (lane >> 3) & 1;
    const int bsw = bn & 7;

    gemm_issue(sbase, tid, m0, Ah, Bhi, Blo, 0);

    for (int kc = 0; kc < 4; kc++) {
        if (kc < 3) {
            gemm_issue(sbase + ((kc + 1) & 1) * GBUF, tid, m0, Ah, Bhi, Blo, kc + 1);
            CP_WAIT1();
        } else {
            CP_WAIT0();
        }
        __syncthreads();
        const uint32_t sb = sbase + (kc & 1) * GBUF;

#pragma unroll
        for (int s = 0; s < 4; s++) {
            const int unit = (s << 1) | aoff;
            uint32_t ah[2][4];
#pragma unroll
            for (int mt = 0; mt < 2; mt++) {
                int arow = wm * 32 + mt * 16 + am;
                ldsm_x4(ah[mt][0], ah[mt][1], ah[mt][2], ah[mt][3],
                        sb + (uint32_t)(arow * 128) + ((unit ^ asw) << 4));
            }
            const int sub = s >> 1;
            const int vhi = ((s & 1) << 1) | boff;
#pragma unroll
            for (int g = 0; g < 4; g++) {
                int brow = wn * 64 + g * 16 + bn;
                uint32_t rb = sb + 16384u + (uint32_t)(sub * 16384 + brow * 128);
                uint32_t bh[4], bl[4];
                ldsm_x4(bh[0], bh[1], bh[2], bh[3], rb + ((vhi ^ bsw) << 4));
                ldsm_x4(bl[0], bl[1], bl[2], bl[3], rb + (((4 | vhi) ^ bsw) << 4));
#pragma unroll
                for (int mt = 0; mt < 2; mt++) {
                    mma_fp16(c[mt][2 * g],     ah[mt], &bh[0]);
                    mma_fp16(c[mt][2 * g],     ah[mt], &bl[0]);
                    mma_fp16(c[mt][2 * g + 1], ah[mt], &bh[2]);
                    mma_fp16(c[mt][2 * g + 1], ah[mt], &bl[2]);
                }
            }
        }
        __syncthreads();
    }

    // ---- epilogue: + bias flag -> g_aggh (fp16) -----------------------------
    const float* __restrict__ bias = p ? b1 : b0;
    __half* __restrict__ dst = g_aggh + (size_t)p * NA * 256;
#pragma unroll
    for (int mt = 0; mt < 2; mt++) {
#pragma unroll
        for (int rr = 0; rr < 2; rr++) {
            int row = m0 + wm * 32 + mt * 16 + rr * 8 + (lane >> 2);
            if (row >= NA) continue;
            float bf = g_cnt[p * NA + row];
            __half* orow = dst + (size_t)row * 256;
#pragma unroll
            for (int n8 = 0; n8 < 8; n8++) {
                int col = h * 128 + wn * 64 + n8 * 8 + (lane & 3) * 2;
                __half2 o = __floats2half2_rn(
                    c[mt][n8][rr * 2 + 0] + bias[col] * bf,
                    c[mt][n8][rr * 2 + 1] + bias[col + 1] * bf);
                *reinterpret_cast<__half2*>(orow + col) = o;
            }
        }
    }
}

// ---------------- finalize + outB zeroing ------------------------------------
#define FIN_BLOCKS ((NA * 32 + 255) / 256)                    // 12500
#define ZB_BLOCKS  ((int)(((size_t)NB * OUT_DIM / 4 + 255) / 256))  // 25000

__global__ __launch_bounds__(256) void finalize_kernel(
    const float* __restrict__ sem, const float* __restrict__ gamma,
    const float* __restrict__ beta, float* __restrict__ outA,
    float* __restrict__ outB)
{
    if (blockIdx.x >= FIN_BLOCKS) {
        size_t i = (size_t)(blockIdx.x - FIN_BLOCKS) * 256 + threadIdx.x;
        if (i < (size_t)NB * OUT_DIM / 4)
            reinterpret_cast<float4*>(outB)[i] = make_float4(0.f, 0.f, 0.f, 0.f);
        return;
    }
    int n = (blockIdx.x * 256 + threadIdx.x) >> 5;
    int lane = threadIdx.x & 31;
    if (n >= NA) return;
    int base = lane * 8;

    const __half* a0p = g_aggh + (size_t)n * 256;
    const __half* a1p = g_aggh + ((size_t)NA + n) * 256;

    float a0[8], a1[8], sv[8];
    {
        uint4 v0 = *reinterpret_cast<const uint4*>(a0p + base);
        uint4 v1 = *reinterpret_cast<const uint4*>(a1p + base);
        const __half2* p0 = reinterpret_cast<const __half2*>(&v0);
        const __half2* p1 = reinterpret_cast<const __half2*>(&v1);
#pragma unroll
        for (int q = 0; q < 4; q++) {
            float2 f0 = __half22float2(p0[q]);
            float2 f1 = __half22float2(p1[q]);
            a0[q * 2] = f0.x; a0[q * 2 + 1] = f0.y;
            a1[q * 2] = f1.x; a1[q * 2 + 1] = f1.y;
        }
    }
    *reinterpret_cast<float4*>(&sv[0]) = *reinterpret_cast<const float4*>(sem + base);
    *reinterpret_cast<float4*>(&sv[4]) = *reinterpret_cast<const float4*>(sem + base + 4);

    float s0 = 0.f, s1 = 0.f;
#pragma unroll
    for (int i = 0; i < 8; i++) {
        s0 += tanhf(a0[i]) * sv[i];
        s1 += tanhf(a1[i]) * sv[i];
    }
#pragma unroll
    for (int o = 16; o > 0; o >>= 1) {
        s0 += __shfl_xor_sync(0xffffffffu, s0, o);
        s1 += __shfl_xor_sync(0xffffffffu, s1, o);
    }
    float m = fmaxf(s0, s1);
    float e0 = __expf(s0 - m), e1 = __expf(s1 - m);
    float w0 = e0 / (e0 + e1);
    float w1 = 1.0f - w0;

    float f[8];
    float sum = 0.f, sq = 0.f;
#pragma unroll
    for (int i = 0; i < 8; i++) {
        f[i] = fmaxf(w0 * a0[i] + w1 * a1[i], 0.f);
        sum += f[i];
        sq  += f[i] * f[i];
    }
#pragma unroll
    for (int o = 16; o > 0; o >>= 1) {
        sum += __shfl_xor_sync(0xffffffffu, sum, o);
        sq  += __shfl_xor_sync(0xffffffffu, sq, o);
    }
    float mu  = sum * (1.0f / 256.0f);
    float var = sq * (1.0f / 256.0f) - mu * mu;
    float rstd = rsqrtf(var + LN_EPS);

    float gm[8], bt[8];
    *reinterpret_cast<float4*>(&gm[0]) = *reinterpret_cast<const float4*>(gamma + base);
    *reinterpret_cast<float4*>(&gm[4]) = *reinterpret_cast<const float4*>(gamma + base + 4);
    *reinterpret_cast<float4*>(&bt[0]) = *reinterpret_cast<const float4*>(beta + base);
    *reinterpret_cast<float4*>(&bt[4]) = *reinterpret_cast<const float4*>(beta + base + 4);

    float o8[8];
#pragma unroll
    for (int i = 0; i < 8; i++)
        o8[i] = (f[i] - mu) * rstd * gm[i] + bt[i];

    float* op = outA + (size_t)n * 256 + base;
    *reinterpret_cast<float4*>(op)     = *reinterpret_cast<float4*>(&o8[0]);
    *reinterpret_cast<float4*>(op + 4) = *reinterpret_cast<float4*>(&o8[4]);
}

// ---------------- launch ----------------------------------------------------
extern "C" void kernel_launch(void* const* d_in, const int* in_sizes, int n_in,
                              void* d_out, int out_size)
{
    const float* x_B  = (const float*)d_in[1];
    const int*   ei0  = (const int*)d_in[2];
    const int*   ei1  = (const int*)d_in[3];
    const float* W0   = (const float*)d_in[4];
    const float* b0   = (const float*)d_in[5];
    const float* W1   = (const float*)d_in[6];
    const float* b1   = (const float*)d_in[7];
    const float* sem  = (const float*)d_in[8];
    const float* gam  = (const float*)d_in[9];
    const float* bet  = (const float*)d_in[10];

    float* outA = (float*)d_out;
    float* outB = outA + (size_t)NA * OUT_DIM;

    cudaFuncSetAttribute(gemm_mma_kernel,
                         cudaFuncAttributeMaxDynamicSharedMemorySize, GSM_TOTAL);

    zero_hist_kernel<<<(NBIN / 4 + 255) / 256, 256>>>();
    splitW_kernel<<<512, 256>>>(W0, W1);

    hist_kernel<<<(2 * NE + 255) / 256, 256>>>(ei0, ei1);
    scanA_kernel<<<NBLK, SCAN_B>>>();
    scanB_kernel<<<1, SCAN_B>>>();
    scanC_kernel<<<NBLK, SCAN_B>>>();
    fill_kernel<<<(2 * NE + 255) / 256, 256>>>(ei0, ei1);

    agg_kernel<<<(NBIN * 32 + 255) / 256, 256>>>(x_B);

    {
        dim3 grid(4, (NA + 127) / 128);
        gemm_mma_kernel<<<grid, 256, GSM_TOTAL>>>(b0, b1);
    }

    finalize_kernel<<<FIN_BLOCKS + ZB_BLOCKS, 256>>>(sem, gam, bet, outA, outB);
}

// round 13
// speedup vs baseline: 1.5966x; 1.2097x over previous
#include <cuda_runtime.h>
#include <cuda_fp16.h>
#include <cstdint>

#define NA 100000
#define NB 100000
#define IN_DIM 256
#define OUT_DIM 256
#define NE 320000
#define LN_EPS 1e-5f

#define NBIN (2 * NA)
#define SCAN_B 512
#define NBLK ((NBIN + SCAN_B - 1) / SCAN_B)   // 391

// ---------------- scratch (device globals; no allocation allowed) -----------
__device__ __half g_aggh[(size_t)2 * NA * 256];      // per-path mean+bias (fp16)
__device__ float g_cnt[NBIN];                        // 1.0 if deg>0 else 0.0
__device__ __half g_Sh[(size_t)NBIN * 256];          // per-bin MEAN, fp16
__device__ __half g_Wt[512 * 256];                   // Wcat^T [n][k], fp16
__device__ int g_hist[NBIN];
__device__ int g_rowptr[NBIN];
__device__ int g_cursor[NBIN];
__device__ int g_elist[2 * NE];
__device__ int g_blocksums[SCAN_B];
__device__ int g_blockoff[SCAN_B];

// ---------------- helpers ----------------------------------------------------
__device__ __forceinline__ uint32_t smem_u32(const void* p) {
    uint32_t a;
    asm("{ .reg .u64 t; cvta.to.shared.u64 t, %1; cvt.u32.u64 %0, t; }" : "=r"(a) : "l"(p));
    return a;
}
__device__ __forceinline__ void ldsm_x4(uint32_t& r0, uint32_t& r1, uint32_t& r2,
                                        uint32_t& r3, uint32_t addr) {
    asm volatile("ldmatrix.sync.aligned.m8n8.x4.shared.b16 {%0,%1,%2,%3}, [%4];"
                 : "=r"(r0), "=r"(r1), "=r"(r2), "=r"(r3) : "r"(addr));
}
__device__ __forceinline__ void mma_fp16(float* c, const uint32_t* a, const uint32_t* b) {
    asm volatile("mma.sync.aligned.m16n8k16.row.col.f32.f16.f16.f32 "
                 "{%0,%1,%2,%3}, {%4,%5,%6,%7}, {%8,%9}, {%0,%1,%2,%3};"
                 : "+f"(c[0]), "+f"(c[1]), "+f"(c[2]), "+f"(c[3])
                 : "r"(a[0]), "r"(a[1]), "r"(a[2]), "r"(a[3]), "r"(b[0]), "r"(b[1]));
}
#define CP_ASYNC16(sm, gp) \
    asm volatile("cp.async.cg.shared.global [%0], [%1], 16;" \
                 :: "r"(sm), "l"(gp) : "memory")
#define CP_ASYNC16Z(sm, gp, sz) \
    asm volatile("cp.async.cg.shared.global [%0], [%1], 16, %2;" \
                 :: "r"(sm), "l"(gp), "r"(sz) : "memory")
#define CP_COMMIT() asm volatile("cp.async.commit_group;" ::: "memory")
#define CP_WAIT0()  asm volatile("cp.async.wait_group 0;" ::: "memory")
#define CP_WAIT1()  asm volatile("cp.async.wait_group 1;" ::: "memory")

// ---------------- zero hist ---------------------------------------------------
__global__ __launch_bounds__(256) void zero_hist_kernel() {
    size_t i = (size_t)blockIdx.x * 256 + threadIdx.x;
    if (i < NBIN / 4)
        reinterpret_cast<int4*>(g_hist)[i] = make_int4(0, 0, 0, 0);
}

// ---------------- W transpose prep -------------------------------------------
__global__ __launch_bounds__(256) void splitW_kernel(const float* __restrict__ W0,
                                                     const float* __restrict__ W1) {
    int n = blockIdx.x;
    int k = threadIdx.x;
    float w = (n < 256) ? W0[k * 256 + n] : W1[k * 256 + (n - 256)];
    g_Wt[n * 256 + k] = __float2half_rn(w);
}

// ---------------- CSR build --------------------------------------------------
__global__ __launch_bounds__(256) void hist_kernel(
    const int* __restrict__ ei0, const int* __restrict__ ei1)
{
    int i = blockIdx.x * 256 + threadIdx.x;
    if (i >= 2 * NE) return;
    int p = (i >= NE) ? 1 : 0;
    int e = i - p * NE;
    const int* __restrict__ ei = p ? ei1 : ei0;
    int dst = ei[e + NE];
    atomicAdd(&g_hist[p * NA + dst], 1);
}

__global__ __launch_bounds__(SCAN_B) void scanA_kernel() {
    __shared__ int sh[SCAN_B];
    int i = blockIdx.x * SCAN_B + threadIdx.x;
    sh[threadIdx.x] = (i < NBIN) ? g_hist[i] : 0;
    __syncthreads();
    for (int d = SCAN_B / 2; d > 0; d >>= 1) {
        if (threadIdx.x < d) sh[threadIdx.x] += sh[threadIdx.x + d];
        __syncthreads();
    }
    if (threadIdx.x == 0) g_blocksums[blockIdx.x] = sh[0];
}

__global__ __launch_bounds__(SCAN_B) void scanB_kernel() {
    __shared__ int sh[SCAN_B];
    int tid = threadIdx.x;
    int v = (tid < NBLK) ? g_blocksums[tid] : 0;
    sh[tid] = v;
    __syncthreads();
    for (int d = 1; d < SCAN_B; d <<= 1) {
        int t = (tid >= d) ? sh[tid - d] : 0;
        __syncthreads();
        sh[tid] += t;
        __syncthreads();
    }
    if (tid < NBLK) g_blockoff[tid] = sh[tid] - v;
}

__global__ __launch_bounds__(SCAN_B) void scanC_kernel() {
    __shared__ int sh[SCAN_B];
    int tid = threadIdx.x;
    int i = blockIdx.x * SCAN_B + tid;
    int v = (i < NBIN) ? g_hist[i] : 0;
    sh[tid] = v;
    __syncthreads();
    for (int d = 1; d < SCAN_B; d <<= 1) {
        int t = (tid >= d) ? sh[tid - d] : 0;
        __syncthreads();
        sh[tid] += t;
        __syncthreads();
    }
    if (i < NBIN) {
        int excl = sh[tid] - v + g_blockoff[blockIdx.x];
        g_rowptr[i] = excl;
        g_cursor[i] = excl;
        g_cnt[i] = (v > 0) ? 1.0f : 0.0f;
    }
}

__global__ __launch_bounds__(256) void fill_kernel(
    const int* __restrict__ ei0, const int* __restrict__ ei1)
{
    int i = blockIdx.x * 256 + threadIdx.x;
    if (i >= 2 * NE) return;
    int p = (i >= NE) ? 1 : 0;
    int e = i - p * NE;
    const int* __restrict__ ei = p ? ei1 : ei0;
    int src = ei[e];
    int dst = ei[e + NE];
    int pos = atomicAdd(&g_cursor[p * NA + dst], 1);
    g_elist[pos] = src;
}

// ---------------- aggregate: warp per bin; mean -> fp16 ----------------------
__global__ __launch_bounds__(256) void agg_kernel(const float* __restrict__ xB) {
    int w = (blockIdx.x * 256 + threadIdx.x) >> 5;
    int lane = threadIdx.x & 31;
    if (w >= NBIN) return;
    int start = g_rowptr[w];
    int deg = g_hist[w];

    float a[8] = {0.f, 0.f, 0.f, 0.f, 0.f, 0.f, 0.f, 0.f};

    int j = 0;
    for (; j + 4 <= deg; j += 4) {
        int s0 = __ldg(&g_elist[start + j]);
        int s1 = __ldg(&g_elist[start + j + 1]);
        int s2 = __ldg(&g_elist[start + j + 2]);
        int s3 = __ldg(&g_elist[start + j + 3]);
        const float4* r0 = reinterpret_cast<const float4*>(xB + (size_t)s0 * 256) + lane * 2;
        const float4* r1 = reinterpret_cast<const float4*>(xB + (size_t)s1 * 256) + lane * 2;
        const float4* r2 = reinterpret_cast<const float4*>(xB + (size_t)s2 * 256) + lane * 2;
        const float4* r3 = reinterpret_cast<const float4*>(xB + (size_t)s3 * 256) + lane * 2;
        float4 v0a = r0[0], v0b = r0[1];
        float4 v1a = r1[0], v1b = r1[1];
        float4 v2a = r2[0], v2b = r2[1];
        float4 v3a = r3[0], v3b = r3[1];
        a[0] += v0a.x + v1a.x + v2a.x + v3a.x;
        a[1] += v0a.y + v1a.y + v2a.y + v3a.y;
        a[2] += v0a.z + v1a.z + v2a.z + v3a.z;
        a[3] += v0a.w + v1a.w + v2a.w + v3a.w;
        a[4] += v0b.x + v1b.x + v2b.x + v3b.x;
        a[5] += v0b.y + v1b.y + v2b.y + v3b.y;
        a[6] += v0b.z + v1b.z + v2b.z + v3b.z;
        a[7] += v0b.w + v1b.w + v2b.w + v3b.w;
    }
    for (; j < deg; j++) {
        int src = __ldg(&g_elist[start + j]);
        const float4* r4 = reinterpret_cast<const float4*>(xB + (size_t)src * 256) + lane * 2;
        float4 v0 = r4[0], v1 = r4[1];
        a[0] += v0.x; a[1] += v0.y; a[2] += v0.z; a[3] += v0.w;
        a[4] += v1.x; a[5] += v1.y; a[6] += v1.z; a[7] += v1.w;
    }

    float inv = (deg > 0) ? 1.0f / (float)deg : 0.0f;
    __half2 h0 = __floats2half2_rn(a[0] * inv, a[1] * inv);
    __half2 h1 = __floats2half2_rn(a[2] * inv, a[3] * inv);
    __half2 h2 = __floats2half2_rn(a[4] * inv, a[5] * inv);
    __half2 h3 = __floats2half2_rn(a[6] * inv, a[7] * inv);
    uint4 hv;
    hv.x = *reinterpret_cast<uint32_t*>(&h0);
    hv.y = *reinterpret_cast<uint32_t*>(&h1);
    hv.z = *reinterpret_cast<uint32_t*>(&h2);
    hv.w = *reinterpret_cast<uint32_t*>(&h3);
    *reinterpret_cast<uint4*>(g_Sh + (size_t)w * 256 + lane * 8) = hv;
}

// ---------------- HMMA GEMM: agg = mean @ W + b (single-pass fp16) -----------
// grid (4, 782): bx = p*2+h, by = m-tile. K-chunk 64.
// Stage = [A 16KB | B 16KB] = 32KB; 2 stages = 64KB.
#define GBUF 32768
#define GSM_TOTAL (2 * GBUF)

__device__ __forceinline__ void gemm_issue(
    uint32_t sb, int tid, int m0,
    const __half* __restrict__ Ah, const __half* __restrict__ Bw,
    int kc)
{
    // A: 128 rows x 64 k fp16 = 1024 x 16B units
#pragma unroll
    for (int l = 0; l < 4; l++) {
        int idx = l * 256 + tid;
        int r = idx >> 3, u = idx & 7;
        int grow = m0 + r;
        int ok = (grow < NA) ? 16 : 0;
        int grc = (grow < NA) ? grow : (NA - 1);
        uint32_t dst = sb + (uint32_t)(r * 128 + ((u ^ (r & 7)) << 4));
        const __half* src = Ah + (size_t)grc * 256 + kc * 64 + u * 8;
        CP_ASYNC16Z(dst, src, ok);
    }
    // B: 128 rows x 64 k fp16 = 1024 x 16B units
#pragma unroll
    for (int l = 0; l < 4; l++) {
        int idx = l * 256 + tid;
        int n = idx >> 3, u = idx & 7;
        uint32_t dst = sb + 16384u + (uint32_t)(n * 128 + ((u ^ (n & 7)) << 4));
        const __half* src = Bw + (size_t)n * 256 + kc * 64 + u * 8;
        CP_ASYNC16(dst, src);
    }
    CP_COMMIT();
}

__global__ __launch_bounds__(256, 2) void gemm_mma_kernel(
    const float* __restrict__ b0, const float* __restrict__ b1)
{
    extern __shared__ char smem[];
    const uint32_t sbase = smem_u32(smem);
    const int tid = threadIdx.x, lane = tid & 31, wid = tid >> 5;
    const int wm = wid & 3;
    const int wn = wid >> 2;
    const int p = blockIdx.x >> 1, h = blockIdx.x & 1;
    const int m0 = blockIdx.y * 128;

    const __half* __restrict__ Ah = g_Sh + (size_t)p * NA * 256;
    const __half* __restrict__ Bw = g_Wt + (size_t)(p * 256 + h * 128) * 256;

    float c[2][8][4];
#pragma unroll
    for (int mt = 0; mt < 2; mt++)
#pragma unroll
        for (int n8 = 0; n8 < 8; n8++)
#pragma unroll
            for (int q = 0; q < 4; q++) c[mt][n8][q] = 0.f;

    const int am = lane & 15;
    const int aoff = lane >> 4;
    const int asw = am & 7;
    const int bn = (lane & 7) | ((lane & 16) >> 1);
    const int boff = (lane >> 3) & 1;
    const int bsw = bn & 7;

    gemm_issue(sbase, tid, m0, Ah, Bw, 0);

    for (int kc = 0; kc < 4; kc++) {
        if (kc < 3) {
            gemm_issue(sbase + ((kc + 1) & 1) * GBUF, tid, m0, Ah, Bw, kc + 1);
            CP_WAIT1();
        } else {
            CP_WAIT0();
        }
        __syncthreads();
        const uint32_t sb = sbase + (kc & 1) * GBUF;

#pragma unroll
        for (int s = 0; s < 4; s++) {
            const int unit = (s << 1) | aoff;
            uint32_t ah[2][4];
#pragma unroll
            for (int mt = 0; mt < 2; mt++) {
                int arow = wm * 32 + mt * 16 + am;
                ldsm_x4(ah[mt][0], ah[mt][1], ah[mt][2], ah[mt][3],
                        sb + (uint32_t)(arow * 128) + ((unit ^ asw) << 4));
            }
            const int vhi = (s << 1) | boff;
#pragma unroll
            for (int g = 0; g < 4; g++) {
                int brow = wn * 64 + g * 16 + bn;
                uint32_t rb = sb + 16384u + (uint32_t)(brow * 128);
                uint32_t bh[4];
                ldsm_x4(bh[0], bh[1], bh[2], bh[3], rb + ((vhi ^ bsw) << 4));
#pragma unroll
                for (int mt = 0; mt < 2; mt++) {
                    mma_fp16(c[mt][2 * g],     ah[mt], &bh[0]);
                    mma_fp16(c[mt][2 * g + 1], ah[mt], &bh[2]);
                }
            }
        }
        __syncthreads();
    }

    // ---- epilogue: + bias flag -> g_aggh (fp16) -----------------------------
    const float* __restrict__ bias = p ? b1 : b0;
    __half* __restrict__ dst = g_aggh + (size_t)p * NA * 256;
#pragma unroll
    for (int mt = 0; mt < 2; mt++) {
#pragma unroll
        for (int rr = 0; rr < 2; rr++) {
            int row = m0 + wm * 32 + mt * 16 + rr * 8 + (lane >> 2);
            if (row >= NA) continue;
            float bf = g_cnt[p * NA + row];
            __half* orow = dst + (size_t)row * 256;
#pragma unroll
            for (int n8 = 0; n8 < 8; n8++) {
                int col = h * 128 + wn * 64 + n8 * 8 + (lane & 3) * 2;
                __half2 o = __floats2half2_rn(
                    c[mt][n8][rr * 2 + 0] + bias[col] * bf,
                    c[mt][n8][rr * 2 + 1] + bias[col + 1] * bf);
                *reinterpret_cast<__half2*>(orow + col) = o;
            }
        }
    }
}

// ---------------- finalize + outB zeroing ------------------------------------
#define FIN_BLOCKS ((NA * 32 + 255) / 256)                    // 12500
#define ZB_BLOCKS  ((int)(((size_t)NB * OUT_DIM / 4 + 255) / 256))  // 25000

__global__ __launch_bounds__(256) void finalize_kernel(
    const float* __restrict__ sem, const float* __restrict__ gamma,
    const float* __restrict__ beta, float* __restrict__ outA,
    float* __restrict__ outB)
{
    if (blockIdx.x >= FIN_BLOCKS) {
        size_t i = (size_t)(blockIdx.x - FIN_BLOCKS) * 256 + threadIdx.x;
        if (i < (size_t)NB * OUT_DIM / 4)
            reinterpret_cast<float4*>(outB)[i] = make_float4(0.f, 0.f, 0.f, 0.f);
        return;
    }
    int n = (blockIdx.x * 256 + threadIdx.x) >> 5;
    int lane = threadIdx.x & 31;
    if (n >= NA) return;
    int base = lane * 8;

    const __half* a0p = g_aggh + (size_t)n * 256;
    const __half* a1p = g_aggh + ((size_t)NA + n) * 256;

    float a0[8], a1[8], sv[8];
    {
        uint4 v0 = *reinterpret_cast<const uint4*>(a0p + base);
        uint4 v1 = *reinterpret_cast<const uint4*>(a1p + base);
        const __half2* p0 = reinterpret_cast<const __half2*>(&v0);
        const __half2* p1 = reinterpret_cast<const __half2*>(&v1);
#pragma unroll
        for (int q = 0; q < 4; q++) {
            float2 f0 = __half22float2(p0[q]);
            float2 f1 = __half22float2(p1[q]);
            a0[q * 2] = f0.x; a0[q * 2 + 1] = f0.y;
            a1[q * 2] = f1.x; a1[q * 2 + 1] = f1.y;
        }
    }
    *reinterpret_cast<float4*>(&sv[0]) = *reinterpret_cast<const float4*>(sem + base);
    *reinterpret_cast<float4*>(&sv[4]) = *reinterpret_cast<const float4*>(sem + base + 4);

    float s0 = 0.f, s1 = 0.f;
#pragma unroll
    for (int i = 0; i < 8; i++) {
        s0 += tanhf(a0[i]) * sv[i];
        s1 += tanhf(a1[i]) * sv[i];
    }
#pragma unroll
    for (int o = 16; o > 0; o >>= 1) {
        s0 += __shfl_xor_sync(0xffffffffu, s0, o);
        s1 += __shfl_xor_sync(0xffffffffu, s1, o);
    }
    float m = fmaxf(s0, s1);
    float e0 = __expf(s0 - m), e1 = __expf(s1 - m);
    float w0 = e0 / (e0 + e1);
    float w1 = 1.0f - w0;

    float f[8];
    float sum = 0.f, sq = 0.f;
#pragma unroll
    for (int i = 0; i < 8; i++) {
        f[i] = fmaxf(w0 * a0[i] + w1 * a1[i], 0.f);
        sum += f[i];
        sq  += f[i] * f[i];
    }
#pragma unroll
    for (int o = 16; o > 0; o >>= 1) {
        sum += __shfl_xor_sync(0xffffffffu, sum, o);
        sq  += __shfl_xor_sync(0xffffffffu, sq, o);
    }
    float mu  = sum * (1.0f / 256.0f);
    float var = sq * (1.0f / 256.0f) - mu * mu;
    float rstd = rsqrtf(var + LN_EPS);

    float gm[8], bt[8];
    *reinterpret_cast<float4*>(&gm[0]) = *reinterpret_cast<const float4*>(gamma + base);
    *reinterpret_cast<float4*>(&gm[4]) = *reinterpret_cast<const float4*>(gamma + base + 4);
    *reinterpret_cast<float4*>(&bt[0]) = *reinterpret_cast<const float4*>(beta + base);
    *reinterpret_cast<float4*>(&bt[4]) = *reinterpret_cast<const float4*>(beta + base + 4);

    float o8[8];
#pragma unroll
    for (int i = 0; i < 8; i++)
        o8[i] = (f[i] - mu) * rstd * gm[i] + bt[i];

    float* op = outA + (size_t)n * 256 + base;
    *reinterpret_cast<float4*>(op)     = *reinterpret_cast<float4*>(&o8[0]);
    *reinterpret_cast<float4*>(op + 4) = *reinterpret_cast<float4*>(&o8[4]);
}

// ---------------- launch ----------------------------------------------------
extern "C" void kernel_launch(void* const* d_in, const int* in_sizes, int n_in,
                              void* d_out, int out_size)
{
    const float* x_B  = (const float*)d_in[1];
    const int*   ei0  = (const int*)d_in[2];
    const int*   ei1  = (const int*)d_in[3];
    const float* W0   = (const float*)d_in[4];
    const float* b0   = (const float*)d_in[5];
    const float* W1   = (const float*)d_in[6];
    const float* b1   = (const float*)d_in[7];
    const float* sem  = (const float*)d_in[8];
    const float* gam  = (const float*)d_in[9];
    const float* bet  = (const float*)d_in[10];

    float* outA = (float*)d_out;
    float* outB = outA + (size_t)NA * OUT_DIM;

    cudaFuncSetAttribute(gemm_mma_kernel,
                         cudaFuncAttributeMaxDynamicSharedMemorySize, GSM_TOTAL);

    zero_hist_kernel<<<(NBIN / 4 + 255) / 256, 256>>>();
    splitW_kernel<<<512, 256>>>(W0, W1);

    hist_kernel<<<(2 * NE + 255) / 256, 256>>>(ei0, ei1);
    scanA_kernel<<<NBLK, SCAN_B>>>();
    scanB_kernel<<<1, SCAN_B>>>();
    scanC_kernel<<<NBLK, SCAN_B>>>();
    fill_kernel<<<(2 * NE + 255) / 256, 256>>>(ei0, ei1);

    agg_kernel<<<(NBIN * 32 + 255) / 256, 256>>>(x_B);

    {
        dim3 grid(4, (NA + 127) / 128);
        gemm_mma_kernel<<<grid, 256, GSM_TOTAL>>>(b0, b1);
    }

    finalize_kernel<<<FIN_BLOCKS + ZB_BLOCKS, 256>>>(sem, gam, bet, outA, outB);
}

// round 14
// speedup vs baseline: 1.6203x; 1.0148x over previous
#include <cuda_runtime.h>
#include <cuda_fp16.h>
#include <cstdint>

#define NA 100000
#define NB 100000
#define IN_DIM 256
#define OUT_DIM 256
#define NE 320000
#define LN_EPS 1e-5f

#define NBIN (2 * NA)
#define SCAN_B 512
#define NBLK ((NBIN + SCAN_B - 1) / SCAN_B)   // 391

// ---------------- scratch (device globals; no allocation allowed) -----------
__device__ __half g_aggh[(size_t)2 * NA * 256];      // per-path mean+bias (fp16)
__device__ float g_cnt[NBIN];                        // 1.0 if deg>0 else 0.0
__device__ __half g_Sh[(size_t)NBIN * 256];          // per-bin MEAN, fp16
__device__ __half g_Wt[512 * 256];                   // Wcat^T [n][k], fp16
__device__ int g_hist[NBIN];
__device__ int g_rowptr[NBIN];
__device__ int g_cursor[NBIN];
__device__ int g_elist[2 * NE];
__device__ int g_blocksums[SCAN_B];

// ---------------- helpers ----------------------------------------------------
__device__ __forceinline__ uint32_t smem_u32(const void* p) {
    uint32_t a;
    asm("{ .reg .u64 t; cvta.to.shared.u64 t, %1; cvt.u32.u64 %0, t; }" : "=r"(a) : "l"(p));
    return a;
}
__device__ __forceinline__ void ldsm_x4(uint32_t& r0, uint32_t& r1, uint32_t& r2,
                                        uint32_t& r3, uint32_t addr) {
    asm volatile("ldmatrix.sync.aligned.m8n8.x4.shared.b16 {%0,%1,%2,%3}, [%4];"
                 : "=r"(r0), "=r"(r1), "=r"(r2), "=r"(r3) : "r"(addr));
}
__device__ __forceinline__ void mma_fp16(float* c, const uint32_t* a, const uint32_t* b) {
    asm volatile("mma.sync.aligned.m16n8k16.row.col.f32.f16.f16.f32 "
                 "{%0,%1,%2,%3}, {%4,%5,%6,%7}, {%8,%9}, {%0,%1,%2,%3};"
                 : "+f"(c[0]), "+f"(c[1]), "+f"(c[2]), "+f"(c[3])
                 : "r"(a[0]), "r"(a[1]), "r"(a[2]), "r"(a[3]), "r"(b[0]), "r"(b[1]));
}
#define CP_ASYNC16(sm, gp) \
    asm volatile("cp.async.cg.shared.global [%0], [%1], 16;" \
                 :: "r"(sm), "l"(gp) : "memory")
#define CP_ASYNC16Z(sm, gp, sz) \
    asm volatile("cp.async.cg.shared.global [%0], [%1], 16, %2;" \
                 :: "r"(sm), "l"(gp), "r"(sz) : "memory")
#define CP_COMMIT() asm volatile("cp.async.commit_group;" ::: "memory")
#define CP_WAIT0()  asm volatile("cp.async.wait_group 0;" ::: "memory")
#define CP_WAIT1()  asm volatile("cp.async.wait_group 1;" ::: "memory")

// ---------------- W transpose prep + hist zero (merged) ----------------------
__global__ __launch_bounds__(256) void splitW_kernel(const float* __restrict__ W0,
                                                     const float* __restrict__ W1) {
    int n = blockIdx.x;
    int k = threadIdx.x;
    float w = (n < 256) ? W0[k * 256 + n] : W1[k * 256 + (n - 256)];
    g_Wt[n * 256 + k] = __float2half_rn(w);

    // merged hist zeroing: 512*256 = 131072 threads >= 50000 int4 stores
    int zi = blockIdx.x * 256 + threadIdx.x;
    if (zi < NBIN / 4)
        reinterpret_cast<int4*>(g_hist)[zi] = make_int4(0, 0, 0, 0);
}

// ---------------- CSR build --------------------------------------------------
__global__ __launch_bounds__(256) void hist_kernel(
    const int* __restrict__ ei0, const int* __restrict__ ei1)
{
    int i = blockIdx.x * 256 + threadIdx.x;
    if (i >= 2 * NE) return;
    int p = (i >= NE) ? 1 : 0;
    int e = i - p * NE;
    const int* __restrict__ ei = p ? ei1 : ei0;
    int dst = ei[e + NE];
    atomicAdd(&g_hist[p * NA + dst], 1);
}

__global__ __launch_bounds__(SCAN_B) void scanA_kernel() {
    __shared__ int sh[SCAN_B];
    int i = blockIdx.x * SCAN_B + threadIdx.x;
    sh[threadIdx.x] = (i < NBIN) ? g_hist[i] : 0;
    __syncthreads();
    for (int d = SCAN_B / 2; d > 0; d >>= 1) {
        if (threadIdx.x < d) sh[threadIdx.x] += sh[threadIdx.x + d];
        __syncthreads();
    }
    if (threadIdx.x == 0) g_blocksums[blockIdx.x] = sh[0];
}

// scanC with merged scanB: each block reduces blocksums[0..bid) itself.
__global__ __launch_bounds__(SCAN_B) void scanC_kernel() {
    __shared__ int sh[SCAN_B];
    __shared__ int sred[SCAN_B];
    int tid = threadIdx.x;
    int bid = blockIdx.x;

    // block offset = sum of blocksums[j] for j < bid
    int v0 = (tid < bid && tid < NBLK) ? g_blocksums[tid] : 0;
    sred[tid] = v0;
    __syncthreads();
    for (int d = SCAN_B / 2; d > 0; d >>= 1) {
        if (tid < d) sred[tid] += sred[tid + d];
        __syncthreads();
    }
    int blockoff = sred[0];

    int i = bid * SCAN_B + tid;
    int v = (i < NBIN) ? g_hist[i] : 0;
    sh[tid] = v;
    __syncthreads();
    for (int d = 1; d < SCAN_B; d <<= 1) {
        int t = (tid >= d) ? sh[tid - d] : 0;
        __syncthreads();
        sh[tid] += t;
        __syncthreads();
    }
    if (i < NBIN) {
        int excl = sh[tid] - v + blockoff;
        g_rowptr[i] = excl;
        g_cursor[i] = excl;
        g_cnt[i] = (v > 0) ? 1.0f : 0.0f;
    }
}

__global__ __launch_bounds__(256) void fill_kernel(
    const int* __restrict__ ei0, const int* __restrict__ ei1)
{
    int i = blockIdx.x * 256 + threadIdx.x;
    if (i >= 2 * NE) return;
    int p = (i >= NE) ? 1 : 0;
    int e = i - p * NE;
    const int* __restrict__ ei = p ? ei1 : ei0;
    int src = ei[e];
    int dst = ei[e + NE];
    int pos = atomicAdd(&g_cursor[p * NA + dst], 1);
    g_elist[pos] = src;
}

// ---------------- aggregate: warp per bin; mean -> fp16 ----------------------
__global__ __launch_bounds__(256) void agg_kernel(const float* __restrict__ xB) {
    int w = (blockIdx.x * 256 + threadIdx.x) >> 5;
    int lane = threadIdx.x & 31;
    if (w >= NBIN) return;
    int start = g_rowptr[w];
    int deg = g_hist[w];

    float a[8] = {0.f, 0.f, 0.f, 0.f, 0.f, 0.f, 0.f, 0.f};

    int j = 0;
    for (; j + 4 <= deg; j += 4) {
        int s0 = __ldg(&g_elist[start + j]);
        int s1 = __ldg(&g_elist[start + j + 1]);
        int s2 = __ldg(&g_elist[start + j + 2]);
        int s3 = __ldg(&g_elist[start + j + 3]);
        const float4* r0 = reinterpret_cast<const float4*>(xB + (size_t)s0 * 256) + lane * 2;
        const float4* r1 = reinterpret_cast<const float4*>(xB + (size_t)s1 * 256) + lane * 2;
        const float4* r2 = reinterpret_cast<const float4*>(xB + (size_t)s2 * 256) + lane * 2;
        const float4* r3 = reinterpret_cast<const float4*>(xB + (size_t)s3 * 256) + lane * 2;
        float4 v0a = r0[0], v0b = r0[1];
        float4 v1a = r1[0], v1b = r1[1];
        float4 v2a = r2[0], v2b = r2[1];
        float4 v3a = r3[0], v3b = r3[1];
        a[0] += v0a.x + v1a.x + v2a.x + v3a.x;
        a[1] += v0a.y + v1a.y + v2a.y + v3a.y;
        a[2] += v0a.z + v1a.z + v2a.z + v3a.z;
        a[3] += v0a.w + v1a.w + v2a.w + v3a.w;
        a[4] += v0b.x + v1b.x + v2b.x + v3b.x;
        a[5] += v0b.y + v1b.y + v2b.y + v3b.y;
        a[6] += v0b.z + v1b.z + v2b.z + v3b.z;
        a[7] += v0b.w + v1b.w + v2b.w + v3b.w;
    }
    for (; j < deg; j++) {
        int src = __ldg(&g_elist[start + j]);
        const float4* r4 = reinterpret_cast<const float4*>(xB + (size_t)src * 256) + lane * 2;
        float4 v0 = r4[0], v1 = r4[1];
        a[0] += v0.x; a[1] += v0.y; a[2] += v0.z; a[3] += v0.w;
        a[4] += v1.x; a[5] += v1.y; a[6] += v1.z; a[7] += v1.w;
    }

    float inv = (deg > 0) ? 1.0f / (float)deg : 0.0f;
    __half2 h0 = __floats2half2_rn(a[0] * inv, a[1] * inv);
    __half2 h1 = __floats2half2_rn(a[2] * inv, a[3] * inv);
    __half2 h2 = __floats2half2_rn(a[4] * inv, a[5] * inv);
    __half2 h3 = __floats2half2_rn(a[6] * inv, a[7] * inv);
    uint4 hv;
    hv.x = *reinterpret_cast<uint32_t*>(&h0);
    hv.y = *reinterpret_cast<uint32_t*>(&h1);
    hv.z = *reinterpret_cast<uint32_t*>(&h2);
    hv.w = *reinterpret_cast<uint32_t*>(&h3);
    *reinterpret_cast<uint4*>(g_Sh + (size_t)w * 256 + lane * 8) = hv;
}

// ---------------- HMMA GEMM: agg = mean @ W + b (single-pass fp16) -----------
// grid (4, 782): bx = p*2+h, by = m-tile. K-chunk 64.
// Stage = [A 16KB | B 16KB] = 32KB; 2 stages = 64KB.
#define GBUF 32768
#define GSM_TOTAL (2 * GBUF)

__device__ __forceinline__ void gemm_issue(
    uint32_t sb, int tid, int m0,
    const __half* __restrict__ Ah, const __half* __restrict__ Bw,
    int kc)
{
#pragma unroll
    for (int l = 0; l < 4; l++) {
        int idx = l * 256 + tid;
        int r = idx >> 3, u = idx & 7;
        int grow = m0 + r;
        int ok = (grow < NA) ? 16 : 0;
        int grc = (grow < NA) ? grow : (NA - 1);
        uint32_t dst = sb + (uint32_t)(r * 128 + ((u ^ (r & 7)) << 4));
        const __half* src = Ah + (size_t)grc * 256 + kc * 64 + u * 8;
        CP_ASYNC16Z(dst, src, ok);
    }
#pragma unroll
    for (int l = 0; l < 4; l++) {
        int idx = l * 256 + tid;
        int n = idx >> 3, u = idx & 7;
        uint32_t dst = sb + 16384u + (uint32_t)(n * 128 + ((u ^ (n & 7)) << 4));
        const __half* src = Bw + (size_t)n * 256 + kc * 64 + u * 8;
        CP_ASYNC16(dst, src);
    }
    CP_COMMIT();
}

__global__ __launch_bounds__(256, 2) void gemm_mma_kernel(
    const float* __restrict__ b0, const float* __restrict__ b1)
{
    extern __shared__ char smem[];
    const uint32_t sbase = smem_u32(smem);
    const int tid = threadIdx.x, lane = tid & 31, wid = tid >> 5;
    const int wm = wid & 3;
    const int wn = wid >> 2;
    const int p = blockIdx.x >> 1, h = blockIdx.x & 1;
    const int m0 = blockIdx.y * 128;

    const __half* __restrict__ Ah = g_Sh + (size_t)p * NA * 256;
    const __half* __restrict__ Bw = g_Wt + (size_t)(p * 256 + h * 128) * 256;

    float c[2][8][4];
#pragma unroll
    for (int mt = 0; mt < 2; mt++)
#pragma unroll
        for (int n8 = 0; n8 < 8; n8++)
#pragma unroll
            for (int q = 0; q < 4; q++) c[mt][n8][q] = 0.f;

    const int am = lane & 15;
    const int aoff = lane >> 4;
    const int asw = am & 7;
    const int bn = (lane & 7) | ((lane & 16) >> 1);
    const int boff = (lane >> 3) & 1;
    const int bsw = bn & 7;

    gemm_issue(sbase, tid, m0, Ah, Bw, 0);

    for (int kc = 0; kc < 4; kc++) {
        if (kc < 3) {
            gemm_issue(sbase + ((kc + 1) & 1) * GBUF, tid, m0, Ah, Bw, kc + 1);
            CP_WAIT1();
        } else {
            CP_WAIT0();
        }
        __syncthreads();
        const uint32_t sb = sbase + (kc & 1) * GBUF;

#pragma unroll
        for (int s = 0; s < 4; s++) {
            const int unit = (s << 1) | aoff;
            uint32_t ah[2][4];
#pragma unroll
            for (int mt = 0; mt < 2; mt++) {
                int arow = wm * 32 + mt * 16 + am;
                ldsm_x4(ah[mt][0], ah[mt][1], ah[mt][2], ah[mt][3],
                        sb + (uint32_t)(arow * 128) + ((unit ^ asw) << 4));
            }
            const int vhi = (s << 1) | boff;
#pragma unroll
            for (int g = 0; g < 4; g++) {
                int brow = wn * 64 + g * 16 + bn;
                uint32_t rb = sb + 16384u + (uint32_t)(brow * 128);
                uint32_t bh[4];
                ldsm_x4(bh[0], bh[1], bh[2], bh[3], rb + ((vhi ^ bsw) << 4));
#pragma unroll
                for (int mt = 0; mt < 2; mt++) {
                    mma_fp16(c[mt][2 * g],     ah[mt], &bh[0]);
                    mma_fp16(c[mt][2 * g + 1], ah[mt], &bh[2]);
                }
            }
        }
        __syncthreads();
    }

    // ---- epilogue: + bias flag -> g_aggh (fp16) -----------------------------
    const float* __restrict__ bias = p ? b1 : b0;
    __half* __restrict__ dst = g_aggh + (size_t)p * NA * 256;
#pragma unroll
    for (int mt = 0; mt < 2; mt++) {
#pragma unroll
        for (int rr = 0; rr < 2; rr++) {
            int row = m0 + wm * 32 + mt * 16 + rr * 8 + (lane >> 2);
            if (row >= NA) continue;
            float bf = g_cnt[p * NA + row];
            __half* orow = dst + (size_t)row * 256;
#pragma unroll
            for (int n8 = 0; n8 < 8; n8++) {
                int col = h * 128 + wn * 64 + n8 * 8 + (lane & 3) * 2;
                __half2 o = __floats2half2_rn(
                    c[mt][n8][rr * 2 + 0] + bias[col] * bf,
                    c[mt][n8][rr * 2 + 1] + bias[col + 1] * bf);
                *reinterpret_cast<__half2*>(orow + col) = o;
            }
        }
    }
}

// ---------------- finalize + outB zeroing (zero blocks FIRST) ----------------
#define FIN_BLOCKS ((NA * 32 + 255) / 256)                    // 12500
#define ZB_BLOCKS  ((int)(((size_t)NB * OUT_DIM / 4 + 255) / 256))  // 25000

__global__ __launch_bounds__(256) void finalize_kernel(
    const float* __restrict__ sem, const float* __restrict__ gamma,
    const float* __restrict__ beta, float* __restrict__ outA,
    float* __restrict__ outB)
{
    if (blockIdx.x < ZB_BLOCKS) {
        size_t i = (size_t)blockIdx.x * 256 + threadIdx.x;
        if (i < (size_t)NB * OUT_DIM / 4)
            reinterpret_cast<float4*>(outB)[i] = make_float4(0.f, 0.f, 0.f, 0.f);
        return;
    }
    int n = ((blockIdx.x - ZB_BLOCKS) * 256 + threadIdx.x) >> 5;
    int lane = threadIdx.x & 31;
    if (n >= NA) return;
    int base = lane * 8;

    const __half* a0p = g_aggh + (size_t)n * 256;
    const __half* a1p = g_aggh + ((size_t)NA + n) * 256;

    float a0[8], a1[8], sv[8];
    {
        uint4 v0 = *reinterpret_cast<const uint4*>(a0p + base);
        uint4 v1 = *reinterpret_cast<const uint4*>(a1p + base);
        const __half2* p0 = reinterpret_cast<const __half2*>(&v0);
        const __half2* p1 = reinterpret_cast<const __half2*>(&v1);
#pragma unroll
        for (int q = 0; q < 4; q++) {
            float2 f0 = __half22float2(p0[q]);
            float2 f1 = __half22float2(p1[q]);
            a0[q * 2] = f0.x; a0[q * 2 + 1] = f0.y;
            a1[q * 2] = f1.x; a1[q * 2 + 1] = f1.y;
        }
    }
    *reinterpret_cast<float4*>(&sv[0]) = *reinterpret_cast<const float4*>(sem + base);
    *reinterpret_cast<float4*>(&sv[4]) = *reinterpret_cast<const float4*>(sem + base + 4);

    float s0 = 0.f, s1 = 0.f;
#pragma unroll
    for (int i = 0; i < 8; i++) {
        s0 += tanhf(a0[i]) * sv[i];
        s1 += tanhf(a1[i]) * sv[i];
    }
#pragma unroll
    for (int o = 16; o > 0; o >>= 1) {
        s0 += __shfl_xor_sync(0xffffffffu, s0, o);
        s1 += __shfl_xor_sync(0xffffffffu, s1, o);
    }
    float m = fmaxf(s0, s1);
    float e0 = __expf(s0 - m), e1 = __expf(s1 - m);
    float w0 = e0 / (e0 + e1);
    float w1 = 1.0f - w0;

    float f[8];
    float sum = 0.f, sq = 0.f;
#pragma unroll
    for (int i = 0; i < 8; i++) {
        f[i] = fmaxf(w0 * a0[i] + w1 * a1[i], 0.f);
        sum += f[i];
        sq  += f[i] * f[i];
    }
#pragma unroll
    for (int o = 16; o > 0; o >>= 1) {
        sum += __shfl_xor_sync(0xffffffffu, sum, o);
        sq  += __shfl_xor_sync(0xffffffffu, sq, o);
    }
    float mu  = sum * (1.0f / 256.0f);
    float var = sq * (1.0f / 256.0f) - mu * mu;
    float rstd = rsqrtf(var + LN_EPS);

    float gm[8], bt[8];
    *reinterpret_cast<float4*>(&gm[0]) = *reinterpret_cast<const float4*>(gamma + base);
    *reinterpret_cast<float4*>(&gm[4]) = *reinterpret_cast<const float4*>(gamma + base + 4);
    *reinterpret_cast<float4*>(&bt[0]) = *reinterpret_cast<const float4*>(beta + base);
    *reinterpret_cast<float4*>(&bt[4]) = *reinterpret_cast<const float4*>(beta + base + 4);

    float o8[8];
#pragma unroll
    for (int i = 0; i < 8; i++)
        o8[i] = (f[i] - mu) * rstd * gm[i] + bt[i];

    float* op = outA + (size_t)n * 256 + base;
    *reinterpret_cast<float4*>(op)     = *reinterpret_cast<float4*>(&o8[0]);
    *reinterpret_cast<float4*>(op + 4) = *reinterpret_cast<float4*>(&o8[4]);
}

// ---------------- launch ----------------------------------------------------
extern "C" void kernel_launch(void* const* d_in, const int* in_sizes, int n_in,
                              void* d_out, int out_size)
{
    const float* x_B  = (const float*)d_in[1];
    const int*   ei0  = (const int*)d_in[2];
    const int*   ei1  = (const int*)d_in[3];
    const float* W0   = (const float*)d_in[4];
    const float* b0   = (const float*)d_in[5];
    const float* W1   = (const float*)d_in[6];
    const float* b1   = (const float*)d_in[7];
    const float* sem  = (const float*)d_in[8];
    const float* gam  = (const float*)d_in[9];
    const float* bet  = (const float*)d_in[10];

    float* outA = (float*)d_out;
    float* outB = outA + (size_t)NA * OUT_DIM;

    cudaFuncSetAttribute(gemm_mma_kernel,
                         cudaFuncAttributeMaxDynamicSharedMemorySize, GSM_TOTAL);

    splitW_kernel<<<512, 256>>>(W0, W1);                 // W prep + hist zero
    hist_kernel<<<(2 * NE + 255) / 256, 256>>>(ei0, ei1);
    scanA_kernel<<<NBLK, SCAN_B>>>();
    scanC_kernel<<<NBLK, SCAN_B>>>();                    // merged scanB+scanC
    fill_kernel<<<(2 * NE + 255) / 256, 256>>>(ei0, ei1);

    agg_kernel<<<(NBIN * 32 + 255) / 256, 256>>>(x_B);

    {
        dim3 grid(4, (NA + 127) / 128);
        gemm_mma_kernel<<<grid, 256, GSM_TOTAL>>>(b0, b1);
    }

    finalize_kernel<<<FIN_BLOCKS + ZB_BLOCKS, 256>>>(sem, gam, bet, outA, outB);
}

// round 15
// speedup vs baseline: 1.6768x; 1.0349x over previous
#include <cuda_runtime.h>
#include <cuda_fp16.h>
#include <cstdint>

#define NA 100000
#define NB 100000
#define IN_DIM 256
#define OUT_DIM 256
#define NE 320000
#define LN_EPS 1e-5f

#define NBIN (2 * NA)
#define SCAN_B 512
#define NBLK ((NBIN + SCAN_B - 1) / SCAN_B)   // 391

// ---------------- scratch (device globals; no allocation allowed) -----------
__device__ __half g_xh[(size_t)NB * 256];            // x_B quantized to fp16
__device__ __half g_aggh[(size_t)2 * NA * 256];      // per-path mean+bias (fp16)
__device__ float g_cnt[NBIN];                        // 1.0 if deg>0 else 0.0
__device__ __half g_Sh[(size_t)NBIN * 256];          // per-bin MEAN, fp16
__device__ __half g_Wt[512 * 256];                   // Wcat^T [n][k], fp16
__device__ int g_hist[NBIN];
__device__ int g_rowptr[NBIN];
__device__ int g_cursor[NBIN];
__device__ int g_elist[2 * NE];
__device__ int g_blocksums[SCAN_B];

// ---------------- helpers ----------------------------------------------------
__device__ __forceinline__ uint32_t smem_u32(const void* p) {
    uint32_t a;
    asm("{ .reg .u64 t; cvta.to.shared.u64 t, %1; cvt.u32.u64 %0, t; }" : "=r"(a) : "l"(p));
    return a;
}
__device__ __forceinline__ void ldsm_x4(uint32_t& r0, uint32_t& r1, uint32_t& r2,
                                        uint32_t& r3, uint32_t addr) {
    asm volatile("ldmatrix.sync.aligned.m8n8.x4.shared.b16 {%0,%1,%2,%3}, [%4];"
                 : "=r"(r0), "=r"(r1), "=r"(r2), "=r"(r3) : "r"(addr));
}
__device__ __forceinline__ void mma_fp16(float* c, const uint32_t* a, const uint32_t* b) {
    asm volatile("mma.sync.aligned.m16n8k16.row.col.f32.f16.f16.f32 "
                 "{%0,%1,%2,%3}, {%4,%5,%6,%7}, {%8,%9}, {%0,%1,%2,%3};"
                 : "+f"(c[0]), "+f"(c[1]), "+f"(c[2]), "+f"(c[3])
                 : "r"(a[0]), "r"(a[1]), "r"(a[2]), "r"(a[3]), "r"(b[0]), "r"(b[1]));
}
#define CP_ASYNC16(sm, gp) \
    asm volatile("cp.async.cg.shared.global [%0], [%1], 16;" \
                 :: "r"(sm), "l"(gp) : "memory")
#define CP_ASYNC16Z(sm, gp, sz) \
    asm volatile("cp.async.cg.shared.global [%0], [%1], 16, %2;" \
                 :: "r"(sm), "l"(gp), "r"(sz) : "memory")
#define CP_COMMIT() asm volatile("cp.async.commit_group;" ::: "memory")
#define CP_WAIT0()  asm volatile("cp.async.wait_group 0;" ::: "memory")
#define CP_WAIT1()  asm volatile("cp.async.wait_group 1;" ::: "memory")

// ---------------- x_B fp32 -> fp16 convert ------------------------------------
__global__ __launch_bounds__(256) void convertX_kernel(const float* __restrict__ xB) {
    size_t i = (size_t)blockIdx.x * 256 + threadIdx.x;   // one uint4 (8 halves)
    const size_t n8 = (size_t)NB * 256 / 8;              // 3,200,000
    if (i >= n8) return;
    const float4* src = reinterpret_cast<const float4*>(xB) + i * 2;
    float4 v0 = src[0], v1 = src[1];
    __half2 h0 = __floats2half2_rn(v0.x, v0.y);
    __half2 h1 = __floats2half2_rn(v0.z, v0.w);
    __half2 h2 = __floats2half2_rn(v1.x, v1.y);
    __half2 h3 = __floats2half2_rn(v1.z, v1.w);
    uint4 o;
    o.x = *reinterpret_cast<uint32_t*>(&h0);
    o.y = *reinterpret_cast<uint32_t*>(&h1);
    o.z = *reinterpret_cast<uint32_t*>(&h2);
    o.w = *reinterpret_cast<uint32_t*>(&h3);
    reinterpret_cast<uint4*>(g_xh)[i] = o;
}

// ---------------- W transpose prep + hist zero (merged) ----------------------
__global__ __launch_bounds__(256) void splitW_kernel(const float* __restrict__ W0,
                                                     const float* __restrict__ W1) {
    int n = blockIdx.x;
    int k = threadIdx.x;
    float w = (n < 256) ? W0[k * 256 + n] : W1[k * 256 + (n - 256)];
    g_Wt[n * 256 + k] = __float2half_rn(w);

    int zi = blockIdx.x * 256 + threadIdx.x;
    if (zi < NBIN / 4)
        reinterpret_cast<int4*>(g_hist)[zi] = make_int4(0, 0, 0, 0);
}

// ---------------- CSR build --------------------------------------------------
__global__ __launch_bounds__(256) void hist_kernel(
    const int* __restrict__ ei0, const int* __restrict__ ei1)
{
    int i = blockIdx.x * 256 + threadIdx.x;
    if (i >= 2 * NE) return;
    int p = (i >= NE) ? 1 : 0;
    int e = i - p * NE;
    const int* __restrict__ ei = p ? ei1 : ei0;
    int dst = ei[e + NE];
    atomicAdd(&g_hist[p * NA + dst], 1);
}

__global__ __launch_bounds__(SCAN_B) void scanA_kernel() {
    __shared__ int sh[SCAN_B];
    int i = blockIdx.x * SCAN_B + threadIdx.x;
    sh[threadIdx.x] = (i < NBIN) ? g_hist[i] : 0;
    __syncthreads();
    for (int d = SCAN_B / 2; d > 0; d >>= 1) {
        if (threadIdx.x < d) sh[threadIdx.x] += sh[threadIdx.x + d];
        __syncthreads();
    }
    if (threadIdx.x == 0) g_blocksums[blockIdx.x] = sh[0];
}

// scanC with merged scanB: each block reduces blocksums[0..bid) itself.
__global__ __launch_bounds__(SCAN_B) void scanC_kernel() {
    __shared__ int sh[SCAN_B];
    __shared__ int sred[SCAN_B];
    int tid = threadIdx.x;
    int bid = blockIdx.x;

    int v0 = (tid < bid && tid < NBLK) ? g_blocksums[tid] : 0;
    sred[tid] = v0;
    __syncthreads();
    for (int d = SCAN_B / 2; d > 0; d >>= 1) {
        if (tid < d) sred[tid] += sred[tid + d];
        __syncthreads();
    }
    int blockoff = sred[0];

    int i = bid * SCAN_B + tid;
    int v = (i < NBIN) ? g_hist[i] : 0;
    sh[tid] = v;
    __syncthreads();
    for (int d = 1; d < SCAN_B; d <<= 1) {
        int t = (tid >= d) ? sh[tid - d] : 0;
        __syncthreads();
        sh[tid] += t;
        __syncthreads();
    }
    if (i < NBIN) {
        int excl = sh[tid] - v + blockoff;
        g_rowptr[i] = excl;
        g_cursor[i] = excl;
        g_cnt[i] = (v > 0) ? 1.0f : 0.0f;
    }
}

__global__ __launch_bounds__(256) void fill_kernel(
    const int* __restrict__ ei0, const int* __restrict__ ei1)
{
    int i = blockIdx.x * 256 + threadIdx.x;
    if (i >= 2 * NE) return;
    int p = (i >= NE) ? 1 : 0;
    int e = i - p * NE;
    const int* __restrict__ ei = p ? ei1 : ei0;
    int src = ei[e];
    int dst = ei[e + NE];
    int pos = atomicAdd(&g_cursor[p * NA + dst], 1);
    g_elist[pos] = src;
}

// ---------------- aggregate: warp per bin; fp16 gather; mean -> fp16 ---------
__global__ __launch_bounds__(256) void agg_kernel() {
    int w = (blockIdx.x * 256 + threadIdx.x) >> 5;
    int lane = threadIdx.x & 31;
    if (w >= NBIN) return;
    int start = g_rowptr[w];
    int deg = g_hist[w];

    float a[8] = {0.f, 0.f, 0.f, 0.f, 0.f, 0.f, 0.f, 0.f};

    int j = 0;
    for (; j + 4 <= deg; j += 4) {
        int s0 = __ldg(&g_elist[start + j]);
        int s1 = __ldg(&g_elist[start + j + 1]);
        int s2 = __ldg(&g_elist[start + j + 2]);
        int s3 = __ldg(&g_elist[start + j + 3]);
        uint4 v0 = *(reinterpret_cast<const uint4*>(g_xh + (size_t)s0 * 256) + lane);
        uint4 v1 = *(reinterpret_cast<const uint4*>(g_xh + (size_t)s1 * 256) + lane);
        uint4 v2 = *(reinterpret_cast<const uint4*>(g_xh + (size_t)s2 * 256) + lane);
        uint4 v3 = *(reinterpret_cast<const uint4*>(g_xh + (size_t)s3 * 256) + lane);
#pragma unroll
        for (int q = 0; q < 4; q++) {
            const uint32_t* pv0 = reinterpret_cast<const uint32_t*>(&v0);
            const uint32_t* pv1 = reinterpret_cast<const uint32_t*>(&v1);
            const uint32_t* pv2 = reinterpret_cast<const uint32_t*>(&v2);
            const uint32_t* pv3 = reinterpret_cast<const uint32_t*>(&v3);
            float2 f0 = __half22float2(*reinterpret_cast<const __half2*>(&pv0[q]));
            float2 f1 = __half22float2(*reinterpret_cast<const __half2*>(&pv1[q]));
            float2 f2 = __half22float2(*reinterpret_cast<const __half2*>(&pv2[q]));
            float2 f3 = __half22float2(*reinterpret_cast<const __half2*>(&pv3[q]));
            a[q * 2]     += f0.x + f1.x + f2.x + f3.x;
            a[q * 2 + 1] += f0.y + f1.y + f2.y + f3.y;
        }
    }
    for (; j < deg; j++) {
        int src = __ldg(&g_elist[start + j]);
        uint4 v = *(reinterpret_cast<const uint4*>(g_xh + (size_t)src * 256) + lane);
        const uint32_t* pv = reinterpret_cast<const uint32_t*>(&v);
#pragma unroll
        for (int q = 0; q < 4; q++) {
            float2 f = __half22float2(*reinterpret_cast<const __half2*>(&pv[q]));
            a[q * 2]     += f.x;
            a[q * 2 + 1] += f.y;
        }
    }

    float inv = (deg > 0) ? 1.0f / (float)deg : 0.0f;
    __half2 h0 = __floats2half2_rn(a[0] * inv, a[1] * inv);
    __half2 h1 = __floats2half2_rn(a[2] * inv, a[3] * inv);
    __half2 h2 = __floats2half2_rn(a[4] * inv, a[5] * inv);
    __half2 h3 = __floats2half2_rn(a[6] * inv, a[7] * inv);
    uint4 hv;
    hv.x = *reinterpret_cast<uint32_t*>(&h0);
    hv.y = *reinterpret_cast<uint32_t*>(&h1);
    hv.z = *reinterpret_cast<uint32_t*>(&h2);
    hv.w = *reinterpret_cast<uint32_t*>(&h3);
    *reinterpret_cast<uint4*>(g_Sh + (size_t)w * 256 + lane * 8) = hv;
}

// ---------------- HMMA GEMM: agg = mean @ W + b (single-pass fp16) -----------
// grid (4, 782): bx = p*2+h, by = m-tile. K-chunk 64.
// Stage = [A 16KB | B 16KB] = 32KB; 2 stages = 64KB.
#define GBUF 32768
#define GSM_TOTAL (2 * GBUF)

__device__ __forceinline__ void gemm_issue(
    uint32_t sb, int tid, int m0,
    const __half* __restrict__ Ah, const __half* __restrict__ Bw,
    int kc)
{
#pragma unroll
    for (int l = 0; l < 4; l++) {
        int idx = l * 256 + tid;
        int r = idx >> 3, u = idx & 7;
        int grow = m0 + r;
        int ok = (grow < NA) ? 16 : 0;
        int grc = (grow < NA) ? grow : (NA - 1);
        uint32_t dst = sb + (uint32_t)(r * 128 + ((u ^ (r & 7)) << 4));
        const __half* src = Ah + (size_t)grc * 256 + kc * 64 + u * 8;
        CP_ASYNC16Z(dst, src, ok);
    }
#pragma unroll
    for (int l = 0; l < 4; l++) {
        int idx = l * 256 + tid;
        int n = idx >> 3, u = idx & 7;
        uint32_t dst = sb + 16384u + (uint32_t)(n * 128 + ((u ^ (n & 7)) << 4));
        const __half* src = Bw + (size_t)n * 256 + kc * 64 + u * 8;
        CP_ASYNC16(dst, src);
    }
    CP_COMMIT();
}

__global__ __launch_bounds__(256, 2) void gemm_mma_kernel(
    const float* __restrict__ b0, const float* __restrict__ b1)
{
    extern __shared__ char smem[];
    const uint32_t sbase = smem_u32(smem);
    const int tid = threadIdx.x, lane = tid & 31, wid = tid >> 5;
    const int wm = wid & 3;
    const int wn = wid >> 2;
    const int p = blockIdx.x >> 1, h = blockIdx.x & 1;
    const int m0 = blockIdx.y * 128;

    const __half* __restrict__ Ah = g_Sh + (size_t)p * NA * 256;
    const __half* __restrict__ Bw = g_Wt + (size_t)(p * 256 + h * 128) * 256;

    float c[2][8][4];
#pragma unroll
    for (int mt = 0; mt < 2; mt++)
#pragma unroll
        for (int n8 = 0; n8 < 8; n8++)
#pragma unroll
            for (int q = 0; q < 4; q++) c[mt][n8][q] = 0.f;

    const int am = lane & 15;
    const int aoff = lane >> 4;
    const int asw = am & 7;
    const int bn = (lane & 7) | ((lane & 16) >> 1);
    const int boff = (lane >> 3) & 1;
    const int bsw = bn & 7;

    gemm_issue(sbase, tid, m0, Ah, Bw, 0);

    for (int kc = 0; kc < 4; kc++) {
        if (kc < 3) {
            gemm_issue(sbase + ((kc + 1) & 1) * GBUF, tid, m0, Ah, Bw, kc + 1);
            CP_WAIT1();
        } else {
            CP_WAIT0();
        }
        __syncthreads();
        const uint32_t sb = sbase + (kc & 1) * GBUF;

#pragma unroll
        for (int s = 0; s < 4; s++) {
            const int unit = (s << 1) | aoff;
            uint32_t ah[2][4];
#pragma unroll
            for (int mt = 0; mt < 2; mt++) {
                int arow = wm * 32 + mt * 16 + am;
                ldsm_x4(ah[mt][0], ah[mt][1], ah[mt][2], ah[mt][3],
                        sb + (uint32_t)(arow * 128) + ((unit ^ asw) << 4));
            }
            const int vhi = (s << 1) | boff;
#pragma unroll
            for (int g = 0; g < 4; g++) {
                int brow = wn * 64 + g * 16 + bn;
                uint32_t rb = sb + 16384u + (uint32_t)(brow * 128);
                uint32_t bh[4];
                ldsm_x4(bh[0], bh[1], bh[2], bh[3], rb + ((vhi ^ bsw) << 4));
#pragma unroll
                for (int mt = 0; mt < 2; mt++) {
                    mma_fp16(c[mt][2 * g],     ah[mt], &bh[0]);
                    mma_fp16(c[mt][2 * g + 1], ah[mt], &bh[2]);
                }
            }
        }
        __syncthreads();
    }

    // ---- epilogue: + bias flag -> g_aggh (fp16) -----------------------------
    const float* __restrict__ bias = p ? b1 : b0;
    __half* __restrict__ dst = g_aggh + (size_t)p * NA * 256;
#pragma unroll
    for (int mt = 0; mt < 2; mt++) {
#pragma unroll
        for (int rr = 0; rr < 2; rr++) {
            int row = m0 + wm * 32 + mt * 16 + rr * 8 + (lane >> 2);
            if (row >= NA) continue;
            float bf = g_cnt[p * NA + row];
            __half* orow = dst + (size_t)row * 256;
#pragma unroll
            for (int n8 = 0; n8 < 8; n8++) {
                int col = h * 128 + wn * 64 + n8 * 8 + (lane & 3) * 2;
                __half2 o = __floats2half2_rn(
                    c[mt][n8][rr * 2 + 0] + bias[col] * bf,
                    c[mt][n8][rr * 2 + 1] + bias[col + 1] * bf);
                *reinterpret_cast<__half2*>(orow + col) = o;
            }
        }
    }
}

// ---------------- finalize + outB zeroing (zero blocks FIRST) ----------------
#define FIN_BLOCKS ((NA * 32 + 255) / 256)                    // 12500
#define ZB_BLOCKS  ((int)(((size_t)NB * OUT_DIM / 4 + 255) / 256))  // 25000

__global__ __launch_bounds__(256) void finalize_kernel(
    const float* __restrict__ sem, const float* __restrict__ gamma,
    const float* __restrict__ beta, float* __restrict__ outA,
    float* __restrict__ outB)
{
    if (blockIdx.x < ZB_BLOCKS) {
        size_t i = (size_t)blockIdx.x * 256 + threadIdx.x;
        if (i < (size_t)NB * OUT_DIM / 4)
            reinterpret_cast<float4*>(outB)[i] = make_float4(0.f, 0.f, 0.f, 0.f);
        return;
    }
    int n = ((blockIdx.x - ZB_BLOCKS) * 256 + threadIdx.x) >> 5;
    int lane = threadIdx.x & 31;
    if (n >= NA) return;
    int base = lane * 8;

    const __half* a0p = g_aggh + (size_t)n * 256;
    const __half* a1p = g_aggh + ((size_t)NA + n) * 256;

    float a0[8], a1[8], sv[8];
    {
        uint4 v0 = *reinterpret_cast<const uint4*>(a0p + base);
        uint4 v1 = *reinterpret_cast<const uint4*>(a1p + base);
        const __half2* p0 = reinterpret_cast<const __half2*>(&v0);
        const __half2* p1 = reinterpret_cast<const __half2*>(&v1);
#pragma unroll
        for (int q = 0; q < 4; q++) {
            float2 f0 = __half22float2(p0[q]);
            float2 f1 = __half22float2(p1[q]);
            a0[q * 2] = f0.x; a0[q * 2 + 1] = f0.y;
            a1[q * 2] = f1.x; a1[q * 2 + 1] = f1.y;
        }
    }
    *reinterpret_cast<float4*>(&sv[0]) = *reinterpret_cast<const float4*>(sem + base);
    *reinterpret_cast<float4*>(&sv[4]) = *reinterpret_cast<const float4*>(sem + base + 4);

    float s0 = 0.f, s1 = 0.f;
#pragma unroll
    for (int i = 0; i < 8; i++) {
        s0 += tanhf(a0[i]) * sv[i];
        s1 += tanhf(a1[i]) * sv[i];
    }
#pragma unroll
    for (int o = 16; o > 0; o >>= 1) {
        s0 += __shfl_xor_sync(0xffffffffu, s0, o);
        s1 += __shfl_xor_sync(0xffffffffu, s1, o);
    }
    float m = fmaxf(s0, s1);
    float e0 = __expf(s0 - m), e1 = __expf(s1 - m);
    float w0 = e0 / (e0 + e1);
    float w1 = 1.0f - w0;

    float f[8];
    float sum = 0.f, sq = 0.f;
#pragma unroll
    for (int i = 0; i < 8; i++) {
        f[i] = fmaxf(w0 * a0[i] + w1 * a1[i], 0.f);
        sum += f[i];
        sq  += f[i] * f[i];
    }
#pragma unroll
    for (int o = 16; o > 0; o >>= 1) {
        sum += __shfl_xor_sync(0xffffffffu, sum, o);
        sq  += __shfl_xor_sync(0xffffffffu, sq, o);
    }
    float mu  = sum * (1.0f / 256.0f);
    float var = sq * (1.0f / 256.0f) - mu * mu;
    float rstd = rsqrtf(var + LN_EPS);

    float gm[8], bt[8];
    *reinterpret_cast<float4*>(&gm[0]) = *reinterpret_cast<const float4*>(gamma + base);
    *reinterpret_cast<float4*>(&gm[4]) = *reinterpret_cast<const float4*>(gamma + base + 4);
    *reinterpret_cast<float4*>(&bt[0]) = *reinterpret_cast<const float4*>(beta + base);
    *reinterpret_cast<float4*>(&bt[4]) = *reinterpret_cast<const float4*>(beta + base + 4);

    float o8[8];
#pragma unroll
    for (int i = 0; i < 8; i++)
        o8[i] = (f[i] - mu) * rstd * gm[i] + bt[i];

    float* op = outA + (size_t)n * 256 + base;
    *reinterpret_cast<float4*>(op)     = *reinterpret_cast<float4*>(&o8[0]);
    *reinterpret_cast<float4*>(op + 4) = *reinterpret_cast<float4*>(&o8[4]);
}

// ---------------- launch ----------------------------------------------------
extern "C" void kernel_launch(void* const* d_in, const int* in_sizes, int n_in,
                              void* d_out, int out_size)
{
    const float* x_B  = (const float*)d_in[1];
    const int*   ei0  = (const int*)d_in[2];
    const int*   ei1  = (const int*)d_in[3];
    const float* W0   = (const float*)d_in[4];
    const float* b0   = (const float*)d_in[5];
    const float* W1   = (const float*)d_in[6];
    const float* b1   = (const float*)d_in[7];
    const float* sem  = (const float*)d_in[8];
    const float* gam  = (const float*)d_in[9];
    const float* bet  = (const float*)d_in[10];

    float* outA = (float*)d_out;
    float* outB = outA + (size_t)NA * OUT_DIM;

    cudaFuncSetAttribute(gemm_mma_kernel,
                         cudaFuncAttributeMaxDynamicSharedMemorySize, GSM_TOTAL);

    splitW_kernel<<<512, 256>>>(W0, W1);                 // W prep + hist zero
    convertX_kernel<<<(int)(((size_t)NB * 256 / 8 + 255) / 256), 256>>>(x_B);
    hist_kernel<<<(2 * NE + 255) / 256, 256>>>(ei0, ei1);
    scanA_kernel<<<NBLK, SCAN_B>>>();
    scanC_kernel<<<NBLK, SCAN_B>>>();                    // merged scanB+scanC
    fill_kernel<<<(2 * NE + 255) / 256, 256>>>(ei0, ei1);

    agg_kernel<<<(NBIN * 32 + 255) / 256, 256>>>();

    {
        dim3 grid(4, (NA + 127) / 128);
        gemm_mma_kernel<<<grid, 256, GSM_TOTAL>>>(b0, b1);
    }

    finalize_kernel<<<FIN_BLOCKS + ZB_BLOCKS, 256>>>(sem, gam, bet, outA, outB);
}

// round 16
// speedup vs baseline: 1.6960x; 1.0115x over previous
#include <cuda_runtime.h>
#include <cuda_fp16.h>
#include <cstdint>

#define NA 100000
#define NB 100000
#define IN_DIM 256
#define OUT_DIM 256
#define NE 320000
#define LN_EPS 1e-5f

#define NBIN (2 * NA)
#define SCAN_B 512
#define NBLK ((NBIN + SCAN_B - 1) / SCAN_B)   // 391

#define CONV_BLOCKS ((int)(((size_t)NB * 256 / 8 + 255) / 256))   // 12500
#define HIST_BLOCKS ((2 * NE + 255) / 256)                        // 2500

// ---------------- scratch (device globals; no allocation allowed) -----------
__device__ __half g_xh[(size_t)NB * 256];            // x_B quantized to fp16
__device__ __half g_aggh[(size_t)2 * NA * 256];      // per-path mean+bias (fp16)
__device__ float g_cnt[NBIN];                        // 1.0 if deg>0 else 0.0
__device__ __half g_Sh[(size_t)NBIN * 256];          // per-bin MEAN, fp16
__device__ __half g_Wt[512 * 256];                   // Wcat^T [n][k], fp16
__device__ int g_hist[NBIN];
__device__ int g_rowptr[NBIN];
__device__ int g_cursor[NBIN];
__device__ int g_elist[2 * NE];
__device__ int g_blocksums[SCAN_B];

// ---------------- helpers ----------------------------------------------------
__device__ __forceinline__ uint32_t smem_u32(const void* p) {
    uint32_t a;
    asm("{ .reg .u64 t; cvta.to.shared.u64 t, %1; cvt.u32.u64 %0, t; }" : "=r"(a) : "l"(p));
    return a;
}
__device__ __forceinline__ void ldsm_x4(uint32_t& r0, uint32_t& r1, uint32_t& r2,
                                        uint32_t& r3, uint32_t addr) {
    asm volatile("ldmatrix.sync.aligned.m8n8.x4.shared.b16 {%0,%1,%2,%3}, [%4];"
                 : "=r"(r0), "=r"(r1), "=r"(r2), "=r"(r3) : "r"(addr));
}
__device__ __forceinline__ void mma_fp16(float* c, const uint32_t* a, const uint32_t* b) {
    asm volatile("mma.sync.aligned.m16n8k16.row.col.f32.f16.f16.f32 "
                 "{%0,%1,%2,%3}, {%4,%5,%6,%7}, {%8,%9}, {%0,%1,%2,%3};"
                 : "+f"(c[0]), "+f"(c[1]), "+f"(c[2]), "+f"(c[3])
                 : "r"(a[0]), "r"(a[1]), "r"(a[2]), "r"(a[3]), "r"(b[0]), "r"(b[1]));
}
#define CP_ASYNC16(sm, gp) \
    asm volatile("cp.async.cg.shared.global [%0], [%1], 16;" \
                 :: "r"(sm), "l"(gp) : "memory")
#define CP_ASYNC16Z(sm, gp, sz) \
    asm volatile("cp.async.cg.shared.global [%0], [%1], 16, %2;" \
                 :: "r"(sm), "l"(gp), "r"(sz) : "memory")
#define CP_COMMIT() asm volatile("cp.async.commit_group;" ::: "memory")
#define CP_WAIT0()  asm volatile("cp.async.wait_group 0;" ::: "memory")
#define CP_WAIT1()  asm volatile("cp.async.wait_group 1;" ::: "memory")

// ---------------- W transpose prep + hist zero (merged) ----------------------
__global__ __launch_bounds__(256) void splitW_kernel(const float* __restrict__ W0,
                                                     const float* __restrict__ W1) {
    int n = blockIdx.x;
    int k = threadIdx.x;
    float w = (n < 256) ? W0[k * 256 + n] : W1[k * 256 + (n - 256)];
    g_Wt[n * 256 + k] = __float2half_rn(w);

    int zi = blockIdx.x * 256 + threadIdx.x;
    if (zi < NBIN / 4)
        reinterpret_cast<int4*>(g_hist)[zi] = make_int4(0, 0, 0, 0);
}

// ---------------- x convert + histogram (merged grid) ------------------------
// blocks [0, CONV_BLOCKS): fp32->fp16 convert of x_B (bandwidth-bound)
// blocks [CONV_BLOCKS, CONV_BLOCKS+HIST_BLOCKS): edge histogram (atomic-bound)
__global__ __launch_bounds__(256) void convhist_kernel(
    const float* __restrict__ xB,
    const int* __restrict__ ei0, const int* __restrict__ ei1)
{
    if (blockIdx.x < CONV_BLOCKS) {
        size_t i = (size_t)blockIdx.x * 256 + threadIdx.x;   // one uint4 (8 halves)
        const size_t n8 = (size_t)NB * 256 / 8;
        if (i >= n8) return;
        const float4* src = reinterpret_cast<const float4*>(xB) + i * 2;
        float4 v0 = src[0], v1 = src[1];
        __half2 h0 = __floats2half2_rn(v0.x, v0.y);
        __half2 h1 = __floats2half2_rn(v0.z, v0.w);
        __half2 h2 = __floats2half2_rn(v1.x, v1.y);
        __half2 h3 = __floats2half2_rn(v1.z, v1.w);
        uint4 o;
        o.x = *reinterpret_cast<uint32_t*>(&h0);
        o.y = *reinterpret_cast<uint32_t*>(&h1);
        o.z = *reinterpret_cast<uint32_t*>(&h2);
        o.w = *reinterpret_cast<uint32_t*>(&h3);
        reinterpret_cast<uint4*>(g_xh)[i] = o;
        return;
    }
    int i = (blockIdx.x - CONV_BLOCKS) * 256 + threadIdx.x;
    if (i >= 2 * NE) return;
    int p = (i >= NE) ? 1 : 0;
    int e = i - p * NE;
    const int* __restrict__ ei = p ? ei1 : ei0;
    int dst = ei[e + NE];
    atomicAdd(&g_hist[p * NA + dst], 1);
}

// ---------------- CSR scan ----------------------------------------------------
__global__ __launch_bounds__(SCAN_B) void scanA_kernel() {
    __shared__ int sh[SCAN_B];
    int i = blockIdx.x * SCAN_B + threadIdx.x;
    sh[threadIdx.x] = (i < NBIN) ? g_hist[i] : 0;
    __syncthreads();
    for (int d = SCAN_B / 2; d > 0; d >>= 1) {
        if (threadIdx.x < d) sh[threadIdx.x] += sh[threadIdx.x + d];
        __syncthreads();
    }
    if (threadIdx.x == 0) g_blocksums[blockIdx.x] = sh[0];
}

// scanC with merged scanB: each block reduces blocksums[0..bid) itself.
__global__ __launch_bounds__(SCAN_B) void scanC_kernel() {
    __shared__ int sh[SCAN_B];
    __shared__ int sred[SCAN_B];
    int tid = threadIdx.x;
    int bid = blockIdx.x;

    int v0 = (tid < bid && tid < NBLK) ? g_blocksums[tid] : 0;
    sred[tid] = v0;
    __syncthreads();
    for (int d = SCAN_B / 2; d > 0; d >>= 1) {
        if (tid < d) sred[tid] += sred[tid + d];
        __syncthreads();
    }
    int blockoff = sred[0];

    int i = bid * SCAN_B + tid;
    int v = (i < NBIN) ? g_hist[i] : 0;
    sh[tid] = v;
    __syncthreads();
    for (int d = 1; d < SCAN_B; d <<= 1) {
        int t = (tid >= d) ? sh[tid - d] : 0;
        __syncthreads();
        sh[tid] += t;
        __syncthreads();
    }
    if (i < NBIN) {
        int excl = sh[tid] - v + blockoff;
        g_rowptr[i] = excl;
        g_cursor[i] = excl;
        g_cnt[i] = (v > 0) ? 1.0f : 0.0f;
    }
}

__global__ __launch_bounds__(256) void fill_kernel(
    const int* __restrict__ ei0, const int* __restrict__ ei1)
{
    int i = blockIdx.x * 256 + threadIdx.x;
    if (i >= 2 * NE) return;
    int p = (i >= NE) ? 1 : 0;
    int e = i - p * NE;
    const int* __restrict__ ei = p ? ei1 : ei0;
    int src = ei[e];
    int dst = ei[e + NE];
    int pos = atomicAdd(&g_cursor[p * NA + dst], 1);
    g_elist[pos] = src;
}

// ---------------- aggregate: warp per bin; fp16 gather; mean -> fp16 ---------
__global__ __launch_bounds__(256) void agg_kernel() {
    int w = (blockIdx.x * 256 + threadIdx.x) >> 5;
    int lane = threadIdx.x & 31;
    if (w >= NBIN) return;
    int start = g_rowptr[w];
    int deg = g_hist[w];

    float a[8] = {0.f, 0.f, 0.f, 0.f, 0.f, 0.f, 0.f, 0.f};

    int j = 0;
    for (; j + 4 <= deg; j += 4) {
        int s0 = __ldg(&g_elist[start + j]);
        int s1 = __ldg(&g_elist[start + j + 1]);
        int s2 = __ldg(&g_elist[start + j + 2]);
        int s3 = __ldg(&g_elist[start + j + 3]);
        uint4 v0 = *(reinterpret_cast<const uint4*>(g_xh + (size_t)s0 * 256) + lane);
        uint4 v1 = *(reinterpret_cast<const uint4*>(g_xh + (size_t)s1 * 256) + lane);
        uint4 v2 = *(reinterpret_cast<const uint4*>(g_xh + (size_t)s2 * 256) + lane);
        uint4 v3 = *(reinterpret_cast<const uint4*>(g_xh + (size_t)s3 * 256) + lane);
#pragma unroll
        for (int q = 0; q < 4; q++) {
            const uint32_t* pv0 = reinterpret_cast<const uint32_t*>(&v0);
            const uint32_t* pv1 = reinterpret_cast<const uint32_t*>(&v1);
            const uint32_t* pv2 = reinterpret_cast<const uint32_t*>(&v2);
            const uint32_t* pv3 = reinterpret_cast<const uint32_t*>(&v3);
            float2 f0 = __half22float2(*reinterpret_cast<const __half2*>(&pv0[q]));
            float2 f1 = __half22float2(*reinterpret_cast<const __half2*>(&pv1[q]));
            float2 f2 = __half22float2(*reinterpret_cast<const __half2*>(&pv2[q]));
            float2 f3 = __half22float2(*reinterpret_cast<const __half2*>(&pv3[q]));
            a[q * 2]     += f0.x + f1.x + f2.x + f3.x;
            a[q * 2 + 1] += f0.y + f1.y + f2.y + f3.y;
        }
    }
    for (; j < deg; j++) {
        int src = __ldg(&g_elist[start + j]);
        uint4 v = *(reinterpret_cast<const uint4*>(g_xh + (size_t)src * 256) + lane);
        const uint32_t* pv = reinterpret_cast<const uint32_t*>(&v);
#pragma unroll
        for (int q = 0; q < 4; q++) {
            float2 f = __half22float2(*reinterpret_cast<const __half2*>(&pv[q]));
            a[q * 2]     += f.x;
            a[q * 2 + 1] += f.y;
        }
    }

    float inv = (deg > 0) ? 1.0f / (float)deg : 0.0f;
    __half2 h0 = __floats2half2_rn(a[0] * inv, a[1] * inv);
    __half2 h1 = __floats2half2_rn(a[2] * inv, a[3] * inv);
    __half2 h2 = __floats2half2_rn(a[4] * inv, a[5] * inv);
    __half2 h3 = __floats2half2_rn(a[6] * inv, a[7] * inv);
    uint4 hv;
    hv.x = *reinterpret_cast<uint32_t*>(&h0);
    hv.y = *reinterpret_cast<uint32_t*>(&h1);
    hv.z = *reinterpret_cast<uint32_t*>(&h2);
    hv.w = *reinterpret_cast<uint32_t*>(&h3);
    *reinterpret_cast<uint4*>(g_Sh + (size_t)w * 256 + lane * 8) = hv;
}

// ---------------- HMMA GEMM: agg = mean @ W + b (single-pass fp16) -----------
// grid (4, 782): bx = p*2+h, by = m-tile. K-chunk 64.
// Stage = [A 16KB | B 16KB] = 32KB; 2 stages = 64KB.
#define GBUF 32768
#define GSM_TOTAL (2 * GBUF)

__device__ __forceinline__ void gemm_issue(
    uint32_t sb, int tid, int m0,
    const __half* __restrict__ Ah, const __half* __restrict__ Bw,
    int kc)
{
#pragma unroll
    for (int l = 0; l < 4; l++) {
        int idx = l * 256 + tid;
        int r = idx >> 3, u = idx & 7;
        int grow = m0 + r;
        int ok = (grow < NA) ? 16 : 0;
        int grc = (grow < NA) ? grow : (NA - 1);
        uint32_t dst = sb + (uint32_t)(r * 128 + ((u ^ (r & 7)) << 4));
        const __half* src = Ah + (size_t)grc * 256 + kc * 64 + u * 8;
        CP_ASYNC16Z(dst, src, ok);
    }
#pragma unroll
    for (int l = 0; l < 4; l++) {
        int idx = l * 256 + tid;
        int n = idx >> 3, u = idx & 7;
        uint32_t dst = sb + 16384u + (uint32_t)(n * 128 + ((u ^ (n & 7)) << 4));
        const __half* src = Bw + (size_t)n * 256 + kc * 64 + u * 8;
        CP_ASYNC16(dst, src);
    }
    CP_COMMIT();
}

__global__ __launch_bounds__(256, 2) void gemm_mma_kernel(
    const float* __restrict__ b0, const float* __restrict__ b1)
{
    extern __shared__ char smem[];
    const uint32_t sbase = smem_u32(smem);
    const int tid = threadIdx.x, lane = tid & 31, wid = tid >> 5;
    const int wm = wid & 3;
    const int wn = wid >> 2;
    const int p = blockIdx.x >> 1, h = blockIdx.x & 1;
    const int m0 = blockIdx.y * 128;

    const __half* __restrict__ Ah = g_Sh + (size_t)p * NA * 256;
    const __half* __restrict__ Bw = g_Wt + (size_t)(p * 256 + h * 128) * 256;

    float c[2][8][4];
#pragma unroll
    for (int mt = 0; mt < 2; mt++)
#pragma unroll
        for (int n8 = 0; n8 < 8; n8++)
#pragma unroll
            for (int q = 0; q < 4; q++) c[mt][n8][q] = 0.f;

    const int am = lane & 15;
    const int aoff = lane >> 4;
    const int asw = am & 7;
    const int bn = (lane & 7) | ((lane & 16) >> 1);
    const int boff = (lane >> 3) & 1;
    const int bsw = bn & 7;

    gemm_issue(sbase, tid, m0, Ah, Bw, 0);

    for (int kc = 0; kc < 4; kc++) {
        if (kc < 3) {
            gemm_issue(sbase + ((kc + 1) & 1) * GBUF, tid, m0, Ah, Bw, kc + 1);
            CP_WAIT1();
        } else {
            CP_WAIT0();
        }
        __syncthreads();
        const uint32_t sb = sbase + (kc & 1) * GBUF;

#pragma unroll
        for (int s = 0; s < 4; s++) {
            const int unit = (s << 1) | aoff;
            uint32_t ah[2][4];
#pragma unroll
            for (int mt = 0; mt < 2; mt++) {
                int arow = wm * 32 + mt * 16 + am;
                ldsm_x4(ah[mt][0], ah[mt][1], ah[mt][2], ah[mt][3],
                        sb + (uint32_t)(arow * 128) + ((unit ^ asw) << 4));
            }
            const int vhi = (s << 1) | boff;
#pragma unroll
            for (int g = 0; g < 4; g++) {
                int brow = wn * 64 + g * 16 + bn;
                uint32_t rb = sb + 16384u + (uint32_t)(brow * 128);
                uint32_t bh[4];
                ldsm_x4(bh[0], bh[1], bh[2], bh[3], rb + ((vhi ^ bsw) << 4));
#pragma unroll
                for (int mt = 0; mt < 2; mt++) {
                    mma_fp16(c[mt][2 * g],     ah[mt], &bh[0]);
                    mma_fp16(c[mt][2 * g + 1], ah[mt], &bh[2]);
                }
            }
        }
        __syncthreads();
    }

    // ---- epilogue: + bias flag -> g_aggh (fp16) -----------------------------
    const float* __restrict__ bias = p ? b1 : b0;
    __half* __restrict__ dst = g_aggh + (size_t)p * NA * 256;
#pragma unroll
    for (int mt = 0; mt < 2; mt++) {
#pragma unroll
        for (int rr = 0; rr < 2; rr++) {
            int row = m0 + wm * 32 + mt * 16 + rr * 8 + (lane >> 2);
            if (row >= NA) continue;
            float bf = g_cnt[p * NA + row];
            __half* orow = dst + (size_t)row * 256;
#pragma unroll
            for (int n8 = 0; n8 < 8; n8++) {
                int col = h * 128 + wn * 64 + n8 * 8 + (lane & 3) * 2;
                __half2 o = __floats2half2_rn(
                    c[mt][n8][rr * 2 + 0] + bias[col] * bf,
                    c[mt][n8][rr * 2 + 1] + bias[col + 1] * bf);
                *reinterpret_cast<__half2*>(orow + col) = o;
            }
        }
    }
}

// ---------------- finalize + outB zeroing (zero blocks FIRST) ----------------
#define FIN_BLOCKS ((NA * 32 + 255) / 256)                    // 12500
#define ZB_BLOCKS  ((int)(((size_t)NB * OUT_DIM / 4 + 255) / 256))  // 25000

__global__ __launch_bounds__(256) void finalize_kernel(
    const float* __restrict__ sem, const float* __restrict__ gamma,
    const float* __restrict__ beta, float* __restrict__ outA,
    float* __restrict__ outB)
{
    if (blockIdx.x < ZB_BLOCKS) {
        size_t i = (size_t)blockIdx.x * 256 + threadIdx.x;
        if (i < (size_t)NB * OUT_DIM / 4)
            reinterpret_cast<float4*>(outB)[i] = make_float4(0.f, 0.f, 0.f, 0.f);
        return;
    }
    int n = ((blockIdx.x - ZB_BLOCKS) * 256 + threadIdx.x) >> 5;
    int lane = threadIdx.x & 31;
    if (n >= NA) return;
    int base = lane * 8;

    const __half* a0p = g_aggh + (size_t)n * 256;
    const __half* a1p = g_aggh + ((size_t)NA + n) * 256;

    float a0[8], a1[8], sv[8];
    {
        uint4 v0 = *reinterpret_cast<const uint4*>(a0p + base);
        uint4 v1 = *reinterpret_cast<const uint4*>(a1p + base);
        const __half2* p0 = reinterpret_cast<const __half2*>(&v0);
        const __half2* p1 = reinterpret_cast<const __half2*>(&v1);
#pragma unroll
        for (int q = 0; q < 4; q++) {
            float2 f0 = __half22float2(p0[q]);
            float2 f1 = __half22float2(p1[q]);
            a0[q * 2] = f0.x; a0[q * 2 + 1] = f0.y;
            a1[q * 2] = f1.x; a1[q * 2 + 1] = f1.y;
        }
    }
    *reinterpret_cast<float4*>(&sv[0]) = *reinterpret_cast<const float4*>(sem + base);
    *reinterpret_cast<float4*>(&sv[4]) = *reinterpret_cast<const float4*>(sem + base + 4);

    float s0 = 0.f, s1 = 0.f;
#pragma unroll
    for (int i = 0; i < 8; i++) {
        s0 += tanhf(a0[i]) * sv[i];
        s1 += tanhf(a1[i]) * sv[i];
    }
#pragma unroll
    for (int o = 16; o > 0; o >>= 1) {
        s0 += __shfl_xor_sync(0xffffffffu, s0, o);
        s1 += __shfl_xor_sync(0xffffffffu, s1, o);
    }
    float m = fmaxf(s0, s1);
    float e0 = __expf(s0 - m), e1 = __expf(s1 - m);
    float w0 = e0 / (e0 + e1);
    float w1 = 1.0f - w0;

    float f[8];
    float sum = 0.f, sq = 0.f;
#pragma unroll
    for (int i = 0; i < 8; i++) {
        f[i] = fmaxf(w0 * a0[i] + w1 * a1[i], 0.f);
        sum += f[i];
        sq  += f[i] * f[i];
    }
#pragma unroll
    for (int o = 16; o > 0; o >>= 1) {
        sum += __shfl_xor_sync(0xffffffffu, sum, o);
        sq  += __shfl_xor_sync(0xffffffffu, sq, o);
    }
    float mu  = sum * (1.0f / 256.0f);
    float var = sq * (1.0f / 256.0f) - mu * mu;
    float rstd = rsqrtf(var + LN_EPS);

    float gm[8], bt[8];
    *reinterpret_cast<float4*>(&gm[0]) = *reinterpret_cast<const float4*>(gamma + base);
    *reinterpret_cast<float4*>(&gm[4]) = *reinterpret_cast<const float4*>(gamma + base + 4);
    *reinterpret_cast<float4*>(&bt[0]) = *reinterpret_cast<const float4*>(beta + base);
    *reinterpret_cast<float4*>(&bt[4]) = *reinterpret_cast<const float4*>(beta + base + 4);

    float o8[8];
#pragma unroll
    for (int i = 0; i < 8; i++)
        o8[i] = (f[i] - mu) * rstd * gm[i] + bt[i];

    float* op = outA + (size_t)n * 256 + base;
    *reinterpret_cast<float4*>(op)     = *reinterpret_cast<float4*>(&o8[0]);
    *reinterpret_cast<float4*>(op + 4) = *reinterpret_cast<float4*>(&o8[4]);
}

// ---------------- launch ----------------------------------------------------
extern "C" void kernel_launch(void* const* d_in, const int* in_sizes, int n_in,
                              void* d_out, int out_size)
{
    const float* x_B  = (const float*)d_in[1];
    const int*   ei0  = (const int*)d_in[2];
    const int*   ei1  = (const int*)d_in[3];
    const float* W0   = (const float*)d_in[4];
    const float* b0   = (const float*)d_in[5];
    const float* W1   = (const float*)d_in[6];
    const float* b1   = (const float*)d_in[7];
    const float* sem  = (const float*)d_in[8];
    const float* gam  = (const float*)d_in[9];
    const float* bet  = (const float*)d_in[10];

    float* outA = (float*)d_out;
    float* outB = outA + (size_t)NA * OUT_DIM;

    cudaFuncSetAttribute(gemm_mma_kernel,
                         cudaFuncAttributeMaxDynamicSharedMemorySize, GSM_TOTAL);

    splitW_kernel<<<512, 256>>>(W0, W1);                     // W prep + hist zero
    convhist_kernel<<<CONV_BLOCKS + HIST_BLOCKS, 256>>>(x_B, ei0, ei1);
    scanA_kernel<<<NBLK, SCAN_B>>>();
    scanC_kernel<<<NBLK, SCAN_B>>>();                        // merged scanB+scanC
    fill_kernel<<<(2 * NE + 255) / 256, 256>>>(ei0, ei1);

    agg_kernel<<<(NBIN * 32 + 255) / 256, 256>>>();

    {
        dim3 grid(4, (NA + 127) / 128);
        gemm_mma_kernel<<<grid, 256, GSM_TOTAL>>>(b0, b1);
    }

    finalize_kernel<<<FIN_BLOCKS + ZB_BLOCKS, 256>>>(sem, gam, bet, outA, outB);
}